// round 15
// baseline (speedup 1.0000x reference)
#include <cuda_runtime.h>
#include <cuda_bf16.h>
#include <math.h>
#include <stdint.h>

#define BATCH 8192

// Activations / weights in gmem, bf16 hi/lo in PERMUTED groups of 4:
//   within each 8-group (32-elem) chunk, group g sits at position pos(g):
//   pos(g) = g<4 ? 2g : 2(g-4)+1  -> thread tg reads groups {tg, tg+4} as ONE 16B load.
__device__ __nv_bfloat16 g_a1[BATCH * 196 * 32];   // conv1 out: [b][px][perm groups]
__device__ __nv_bfloat16 g_a2[BATCH * 49 * 64];    // conv2 out: [b][px][2 halves x perm groups]
__device__ __nv_bfloat16 g_a3[BATCH * 2048];       // conv3 out (std interleave, fc1 order)
__device__ float g_a4[BATCH * 256];                // fc1 out
__device__ __nv_bfloat16 g_fw1[256 * 2048];        // fc1 W (std interleave)
__device__ __nv_bfloat16 g_w2i[32 * 800];          // conv2 W: [oc][off*32 + pos*4]
__device__ __nv_bfloat16 g_w3i[64 * 1600];         // conv3 W: [oc][off*64 + half*32 + pos*4]

__device__ __forceinline__ int gpos(int g) { return (g < 4) ? 2 * g : 2 * (g - 4) + 1; }

__device__ __forceinline__ uint16_t bfbits(__nv_bfloat16 x) {
    return *reinterpret_cast<uint16_t*>(&x);
}
__device__ __forceinline__ void bf16split(float v, __nv_bfloat16& h, __nv_bfloat16& l) {
    h = __float2bfloat16(v);
    l = __float2bfloat16(v - __bfloat162float(h));
}
__device__ __forceinline__ uint2 pack4(float v0, float v1) {
    __nv_bfloat16 h0, l0, h1, l1;
    bf16split(v0, h0, l0);
    bf16split(v1, h1, l1);
    uint2 r;
    r.x = (uint32_t)bfbits(h0) | ((uint32_t)bfbits(h1) << 16);
    r.y = (uint32_t)bfbits(l0) | ((uint32_t)bfbits(l1) << 16);
    return r;
}

__device__ __forceinline__ void mma_bf16(float* c,
                                         uint32_t a0, uint32_t a1, uint32_t a2, uint32_t a3,
                                         uint32_t b0, uint32_t b1) {
    asm volatile(
        "mma.sync.aligned.m16n8k16.row.col.f32.bf16.bf16.f32 "
        "{%0,%1,%2,%3}, {%4,%5,%6,%7}, {%8,%9}, {%0,%1,%2,%3};"
        : "+f"(c[0]), "+f"(c[1]), "+f"(c[2]), "+f"(c[3])
        : "r"(a0), "r"(a1), "r"(a2), "r"(a3), "r"(b0), "r"(b1));
}

__device__ __forceinline__ uint32_t smem_u32(const void* p) {
    return (uint32_t)__cvta_generic_to_shared(p);
}
__device__ __forceinline__ uint4 lds128(uint32_t addr) {
    uint4 r;
    asm("ld.shared.v4.u32 {%0,%1,%2,%3}, [%4];"
        : "=r"(r.x), "=r"(r.y), "=r"(r.z), "=r"(r.w) : "r"(addr));
    return r;
}
__device__ __forceinline__ uint2 lds64(uint32_t addr) {
    uint2 r;
    asm("ld.shared.v2.u32 {%0,%1}, [%2];" : "=r"(r.x), "=r"(r.y) : "r"(addr));
    return r;
}
__device__ __forceinline__ uint32_t lds16(uint32_t addr) {
    uint32_t r;
    asm("ld.shared.u16 %0, [%1];" : "=r"(r) : "r"(addr));
    return r;
}
__device__ __forceinline__ uint2 lds_u64(const __nv_bfloat16* p, int elem_idx) {
    return *reinterpret_cast<const uint2*>(p + elem_idx);
}
__device__ __forceinline__ uint32_t pk(uint32_t lo, uint32_t hi) {
    return lo | (hi << 16);
}

// cp.async helpers (16B)
__device__ __forceinline__ void cp16(void* smem_dst, const void* gmem_src) {
    uint32_t d = (uint32_t)__cvta_generic_to_shared(smem_dst);
    asm volatile("cp.async.cg.shared.global [%0], [%1], 16;\n" :: "r"(d), "l"(gmem_src));
}
#define CP_COMMIT() asm volatile("cp.async.commit_group;\n" ::: "memory")
#define CP_WAIT(n)  asm volatile("cp.async.wait_group %0;\n" :: "n"(n) : "memory")

// ---------------- merged prep kernel (PERMUTED conv weight layouts) ----------------
__global__ void __launch_bounds__(256) k_prep(const float* __restrict__ fw1,
                                              const float* __restrict__ w2,
                                              const float* __restrict__ w3) {
    int i = blockIdx.x * 256 + threadIdx.x;   // 131072 total
    {
        int row = i >> 9, p = i & 511;
        uint2 v = pack4(fw1[row * 1024 + 2 * p], fw1[row * 1024 + 2 * p + 1]);
        *reinterpret_cast<uint2*>(g_fw1 + row * 2048 + p * 4) = v;
    }
    if (i < 6400) {
        int oc = i / 200, r = i - oc * 200;
        int off = r >> 3, p = r & 7;   // p = ic-pair group (16 ic -> 8 groups)
        uint2 v = pack4(w2[oc * 400 + (2 * p) * 25 + off], w2[oc * 400 + (2 * p + 1) * 25 + off]);
        *reinterpret_cast<uint2*>(g_w2i + oc * 800 + off * 32 + gpos(p) * 4) = v;
    }
    if (i < 25600) {
        int oc = i / 400, r = i - oc * 400;
        int off = r >> 4, p = r & 15;  // p = ic-pair group (32 ic -> 16 groups, 2 halves)
        uint2 v = pack4(w3[oc * 800 + (2 * p) * 25 + off], w3[oc * 800 + (2 * p + 1) * 25 + off]);
        *reinterpret_cast<uint2*>(g_w3i + oc * 1600 + off * 64 + (p >> 3) * 32 + gpos(p & 7) * 4) = v;
    }
}

// ---------------- conv1 (1->16) via bf16x3 MMA, weights-as-A ----------------
#define C1_SMEM 70496
__global__ void __launch_bounds__(512) k_conv1(const float* __restrict__ x,
                                               const float* __restrict__ w1,
                                               const float* __restrict__ b1) {
    extern __shared__ char smem[];
    __nv_bfloat16* s_hi = (__nv_bfloat16*)(smem);            // 4488 elem (4 x 34x33)
    __nv_bfloat16* s_lo = (__nv_bfloat16*)(smem + 8976);     // 4488 elem
    __nv_bfloat16* s_w  = (__nv_bfloat16*)(smem + 17952);    // 16 x 72 elem interleaved
    int*           s_pool = (int*)(smem + 20256);            // 4*196*16
    float*         s_bias = (float*)(smem + 70432);

    const int img0 = blockIdx.x * 4;
    const int tid = threadIdx.x;
    const int warp = tid >> 5;
    const int lane = tid & 31;
    const int gid = lane >> 2;
    const int tg  = lane & 3;

    for (int i = tid; i < 4488; i += 512) ((uint32_t*)smem)[i] = 0u;
    for (int i = tid; i < 12544; i += 512) s_pool[i] = 0;
    if (tid < 16) s_bias[tid] = b1[tid];
    if (tid < 256) {
        int oc = tid >> 4, p = tid & 15;
        int k0 = 2 * p, k1 = 2 * p + 1;
        float v0 = (k0 < 25) ? w1[oc * 25 + k0] : 0.f;
        float v1 = (k1 < 25) ? w1[oc * 25 + k1] : 0.f;
        *reinterpret_cast<uint2*>(s_w + oc * 72 + p * 4) = pack4(v0, v1);
    }
    __syncthreads();
    for (int i = tid; i < 3136; i += 512) {
        int img = i / 784, px = i - img * 784;
        int iy = px / 28, ix = px - iy * 28;
        __nv_bfloat16 h, l;
        bf16split(x[(img0 + img) * 784 + px], h, l);
        int d = img * 1122 + (iy + 2) * 33 + (ix + 2);
        s_hi[d] = h; s_lo[d] = l;
    }
    __syncthreads();

    uint32_t Ah[2][4], Al[2][4];
#pragma unroll
    for (int s = 0; s < 2; s++) {
        uint2 g0 = lds_u64(s_w, gid * 72 + (tg + 8 * s) * 4);
        uint2 g1 = lds_u64(s_w, (gid + 8) * 72 + (tg + 8 * s) * 4);
        uint2 g2 = lds_u64(s_w, gid * 72 + (tg + 4 + 8 * s) * 4);
        uint2 g3 = lds_u64(s_w, (gid + 8) * 72 + (tg + 4 + 8 * s) * 4);
        Ah[s][0] = g0.x; Al[s][0] = g0.y;
        Ah[s][1] = g1.x; Al[s][1] = g1.y;
        Ah[s][2] = g2.x; Al[s][2] = g2.y;
        Ah[s][3] = g3.x; Al[s][3] = g3.y;
    }

    int doffB[8];
    {
        int kk[8] = {2 * tg, 2 * tg + 1, 2 * tg + 8, 2 * tg + 9,
                     2 * tg + 16, 2 * tg + 17, 2 * tg + 24, 2 * tg + 25};
#pragma unroll
        for (int j = 0; j < 8; j++) {
            int ky = kk[j] / 5, kx = kk[j] - ky * 5;
            doffB[j] = (ky * 33 + kx) * 2;
        }
    }
    const uint32_t hiB = smem_u32(s_hi);
    const uint32_t loB = smem_u32(s_lo);

    const float bb0 = s_bias[gid], bb1 = s_bias[gid + 8];

#pragma unroll 1
    for (int ti = 0; ti < 13; ti++) {
#pragma unroll
        for (int half = 0; half < 2; half++) {
            int t = warp + 16 * (2 * ti + half);
            if (t < 392) {
                int img = t / 98, tb = t - img * 98;
                int pxg = tb * 8 + gid;
                int yg = pxg / 28, xg = pxg - yg * 28;
                uint32_t abB = (uint32_t)(img * 1122 + yg * 33 + xg) * 2;
                uint32_t pH = hiB + abB, pL = loB + abB;

                uint32_t bh0 = pk(lds16(pH + doffB[0]), lds16(pH + doffB[1]));
                uint32_t bh1 = pk(lds16(pH + doffB[2]), lds16(pH + doffB[3]));
                uint32_t bh2 = pk(lds16(pH + doffB[4]), lds16(pH + doffB[5]));
                uint32_t bh3 = pk(lds16(pH + doffB[6]), lds16(pH + doffB[7]));
                uint32_t bl0 = pk(lds16(pL + doffB[0]), lds16(pL + doffB[1]));
                uint32_t bl1 = pk(lds16(pL + doffB[2]), lds16(pL + doffB[3]));
                uint32_t bl2 = pk(lds16(pL + doffB[4]), lds16(pL + doffB[5]));
                uint32_t bl3 = pk(lds16(pL + doffB[6]), lds16(pL + doffB[7]));

                float c[4] = {0.f, 0.f, 0.f, 0.f};
                mma_bf16(c, Ah[0][0], Ah[0][1], Ah[0][2], Ah[0][3], bh0, bh1);
                mma_bf16(c, Ah[1][0], Ah[1][1], Ah[1][2], Ah[1][3], bh2, bh3);
                mma_bf16(c, Ah[0][0], Ah[0][1], Ah[0][2], Ah[0][3], bl0, bl1);
                mma_bf16(c, Ah[1][0], Ah[1][1], Ah[1][2], Ah[1][3], bl2, bl3);
                mma_bf16(c, Al[0][0], Al[0][1], Al[0][2], Al[0][3], bh0, bh1);
                mma_bf16(c, Al[1][0], Al[1][1], Al[1][2], Al[1][3], bh2, bh3);

                int pxo = tb * 8 + 2 * tg;
                int yo = pxo / 28, xo = pxo - yo * 28;
                int sp = (yo >> 1) * 14 + (xo >> 1);
                float v0 = fmaxf(c[0] + bb0, 0.f);
                float v1 = fmaxf(c[1] + bb0, 0.f);
                float v2 = fmaxf(c[2] + bb1, 0.f);
                float v3 = fmaxf(c[3] + bb1, 0.f);
                atomicMax(&s_pool[img * 3136 + sp * 16 + gid], __float_as_int(fmaxf(v0, v1)));
                atomicMax(&s_pool[img * 3136 + sp * 16 + gid + 8], __float_as_int(fmaxf(v2, v3)));
            }
        }
    }
    __syncthreads();
    // write g_a1 with PERMUTED group order (conv2 expects pos(g))
    for (int i = tid; i < 6272; i += 512) {
        int img = i / 1568, rr = i - img * 1568;
        int sp = rr >> 3, p = rr & 7;
        float v0 = __int_as_float(s_pool[img * 3136 + sp * 16 + 2 * p]);
        float v1 = __int_as_float(s_pool[img * 3136 + sp * 16 + 2 * p + 1]);
        *reinterpret_cast<uint2*>(g_a1 + ((img0 + img) * 196 + sp) * 32 + gpos(p) * 4) = pack4(v0, v1);
    }
}

// ---------------- conv2 (16->32): 4 img/block, 512 thr, LDS.128 fragments ----------------
#define C2_SMEM 201984
__global__ void __launch_bounds__(512) k_conv2(const float* __restrict__ b2) {
    extern __shared__ char smem[];
    __nv_bfloat16* s_in = (__nv_bfloat16*)(smem);               // 62208 elem
    __nv_bfloat16* s_w  = (__nv_bfloat16*)(smem + 124416);      // 26112 elem
    int*           s_pool = (int*)(smem + 176640);              // 6272 int
    float*         s_bias = (float*)(smem + 201728);

    const int img0 = blockIdx.x * 4;
    const int tid = threadIdx.x;
    const int warp = tid >> 5;
    const int lane = tid & 31;
    const int gid = lane >> 2;
    const int tg  = lane & 3;

    uint4 z4 = {0, 0, 0, 0};
    for (int i = tid; i < 7776; i += 512) ((uint4*)s_in)[i] = z4;
    for (int i = tid; i < 6272; i += 512) s_pool[i] = 0;
    if (tid < 32) s_bias[tid] = b2[tid];
    __syncthreads();
    for (int i = tid; i < 3200; i += 512) {
        int oc = i / 100, r = i - oc * 100;
        cp16(s_w + oc * 816 + r * 8, g_w2i + oc * 800 + r * 8);
    }
    for (int i = tid; i < 3136; i += 512) {
        int img = i / 784, r = i - img * 784;
        int px = r >> 2, q = r & 3;
        int y = px / 14, xx = px - y * 14;
        cp16(s_in + img * 15552 + ((y + 2) * 18 + (xx + 2)) * 48 + q * 8,
             g_a1 + ((img0 + img) * 196 + px) * 32 + q * 8);
    }
    CP_COMMIT();
    CP_WAIT(0);
    __syncthreads();

    const uint32_t inB = smem_u32(s_in);
    const uint32_t wBs = smem_u32(s_w);
    uint32_t a0B[4], a1B[4];
#pragma unroll
    for (int ti = 0; ti < 4; ti++) {
        int t = warp + 16 * ti;
        if (t < 49) {
            int r0 = t * 16 + gid, r1 = r0 + 8;
            int i0 = r0 / 196, p0 = r0 - i0 * 196;
            int i1 = r1 / 196, p1 = r1 - i1 * 196;
            int y0 = p0 / 14, x0 = p0 - y0 * 14;
            int y1 = p1 / 14, x1 = p1 - y1 * 14;
            a0B[ti] = inB + (uint32_t)(i0 * 15552 + (y0 * 18 + x0) * 48) * 2 + tg * 16;
            a1B[ti] = inB + (uint32_t)(i1 * 15552 + (y1 * 18 + x1) * 48) * 2 + tg * 16;
        }
    }
    uint32_t wB[4];
#pragma unroll
    for (int nt = 0; nt < 4; nt++) wB[nt] = wBs + (uint32_t)((nt * 8 + gid) * 816) * 2 + tg * 16;

    float acc[4][4][4];
#pragma unroll
    for (int ti = 0; ti < 4; ti++)
#pragma unroll
        for (int nt = 0; nt < 4; nt++)
#pragma unroll
            for (int j = 0; j < 4; j++) acc[ti][nt][j] = 0.f;

#pragma unroll
    for (int off = 0; off < 25; off++) {
        const int dy = off / 5, dx = off - dy * 5;
        const uint32_t dpixB = (uint32_t)((dy * 18 + dx) * 48) * 2;
        const uint32_t wofsB = (uint32_t)(off * 32) * 2;
        // W fragments: one LDS.128 per nt-row -> {hi0, lo0, hi1, lo1}
        uint4 w[4];
#pragma unroll
        for (int nt = 0; nt < 4; nt++) w[nt] = lds128(wB[nt] + wofsB);
#pragma unroll
        for (int ti = 0; ti < 4; ti++) {
            int t = warp + 16 * ti;
            if (t < 49) {
                uint4 u0 = lds128(a0B[ti] + dpixB);
                uint4 u1 = lds128(a1B[ti] + dpixB);
#pragma unroll
                for (int nt = 0; nt < 4; nt++)
                    mma_bf16(acc[ti][nt], u0.x, u1.x, u0.z, u1.z, w[nt].x, w[nt].z);
#pragma unroll
                for (int nt = 0; nt < 4; nt++)
                    mma_bf16(acc[ti][nt], u0.x, u1.x, u0.z, u1.z, w[nt].y, w[nt].w);
#pragma unroll
                for (int nt = 0; nt < 4; nt++)
                    mma_bf16(acc[ti][nt], u0.y, u1.y, u0.w, u1.w, w[nt].x, w[nt].z);
            }
        }
    }

#pragma unroll
    for (int ti = 0; ti < 4; ti++) {
        int t = warp + 16 * ti;
        if (t < 49) {
            int r0 = t * 16 + gid, r1 = r0 + 8;
            int i0 = r0 / 196, p0 = r0 - i0 * 196;
            int i1 = r1 / 196, p1 = r1 - i1 * 196;
            int y0 = p0 / 14, x0 = p0 - y0 * 14;
            int y1 = p1 / 14, x1 = p1 - y1 * 14;
            int pi0 = i0 * 1568 + ((y0 >> 1) * 7 + (x0 >> 1)) * 32;
            int pi1 = i1 * 1568 + ((y1 >> 1) * 7 + (x1 >> 1)) * 32;
#pragma unroll
            for (int nt = 0; nt < 4; nt++) {
                int col = nt * 8 + tg * 2;
                float bb0 = s_bias[col], bb1 = s_bias[col + 1];
                float v0 = fmaxf(acc[ti][nt][0] + bb0, 0.f);
                float v1 = fmaxf(acc[ti][nt][1] + bb1, 0.f);
                float v2 = fmaxf(acc[ti][nt][2] + bb0, 0.f);
                float v3 = fmaxf(acc[ti][nt][3] + bb1, 0.f);
                float q0 = __shfl_xor_sync(0xffffffffu, v0, 4);
                float q1 = __shfl_xor_sync(0xffffffffu, v1, 4);
                float q2 = __shfl_xor_sync(0xffffffffu, v2, 4);
                float q3 = __shfl_xor_sync(0xffffffffu, v3, 4);
                if ((gid & 1) == 0) {
                    atomicMax(&s_pool[pi0 + col], __float_as_int(fmaxf(v0, q0)));
                    atomicMax(&s_pool[pi0 + col + 1], __float_as_int(fmaxf(v1, q1)));
                    atomicMax(&s_pool[pi1 + col], __float_as_int(fmaxf(v2, q2)));
                    atomicMax(&s_pool[pi1 + col + 1], __float_as_int(fmaxf(v3, q3)));
                }
            }
        }
    }
    __syncthreads();
    // write g_a2 with PERMUTED group order within each 32-elem half
    for (int i = tid; i < 3136; i += 512) {
        int img = i / 784, r = i - img * 784;
        int px = r >> 4, p = r & 15;
        float v0 = __int_as_float(s_pool[img * 1568 + px * 32 + 2 * p]);
        float v1 = __int_as_float(s_pool[img * 1568 + px * 32 + 2 * p + 1]);
        int dsto = (p >> 3) * 32 + gpos(p & 7) * 4;
        *reinterpret_cast<uint2*>(g_a2 + ((img0 + img) * 49 + px) * 64 + dsto) = pack4(v0, v1);
    }
}

// ---------------- conv3 (32->64): 3 img x 16-oc, 320 thr, LDS.128 fragments ----------------
#define C3_SMEM 113056
__global__ void __launch_bounds__(320, 2) k_conv3(const float* __restrict__ b3) {
    extern __shared__ char smem[];
    __nv_bfloat16* s_in = (__nv_bfloat16*)(smem);               // 29040 elem
    __nv_bfloat16* s_w  = (__nv_bfloat16*)(smem + 58080);       // 25856 elem
    int*           s_pool = (int*)(smem + 109792);              // 768 int
    float*         s_bias = (float*)(smem + 112864);            // 16

    const int img0 = blockIdx.x * 3;
    const int g = blockIdx.y;        // oc-group 0..3 (16 oc each)
    const int tid = threadIdx.x;
    const int warp = tid >> 5;       // 0..9 -> m-tile
    const int lane = tid & 31;
    const int gid = lane >> 2;
    const int tg  = lane & 3;

    uint4 z4 = {0, 0, 0, 0};
    for (int i = tid; i < 3630; i += 320) ((uint4*)s_in)[i] = z4;
    for (int i = tid; i < 768; i += 320) s_pool[i] = 0;
    if (tid < 16) s_bias[tid] = b3[g * 16 + tid];
    __syncthreads();
    const __nv_bfloat16* wg = g_w3i + g * 16 * 1600;
    for (int i = tid; i < 3200; i += 320) {
        int ocl = i / 200, r = i - ocl * 200;
        cp16(s_w + ocl * 1616 + r * 8, wg + ocl * 1600 + r * 8);
    }
    for (int i = tid; i < 1176; i += 320) {
        int img = i / 392, r = i - img * 392;
        if (img0 + img < BATCH) {
            int px = r >> 3, q = r & 7;
            int y = px / 7, xx = px - y * 7;
            cp16(s_in + img * 9680 + ((y + 2) * 11 + (xx + 2)) * 80 + q * 8,
                 g_a2 + ((img0 + img) * 49 + px) * 64 + q * 8);
        }
    }
    CP_COMMIT();
    CP_WAIT(0);
    __syncthreads();

    int r0 = warp * 16 + gid, r1 = r0 + 8;
    int rc0 = r0 < 146 ? r0 : 146;
    int rc1 = r1 < 146 ? r1 : 146;
    int i0 = rc0 / 49, p0 = rc0 - i0 * 49;
    int i1 = rc1 / 49, p1 = rc1 - i1 * 49;
    int y0 = p0 / 7, x0 = p0 - y0 * 7;
    int y1 = p1 / 7, x1 = p1 - y1 * 7;
    const uint32_t inB = smem_u32(s_in);
    const uint32_t wBs = smem_u32(s_w);
    const uint32_t a0B = inB + (uint32_t)(i0 * 9680 + (y0 * 11 + x0) * 80) * 2 + tg * 16;
    const uint32_t a1B = inB + (uint32_t)(i1 * 9680 + (y1 * 11 + x1) * 80) * 2 + tg * 16;
    const uint32_t w0B = wBs + (uint32_t)(gid * 1616) * 2 + tg * 16;
    const uint32_t w1B = wBs + (uint32_t)((8 + gid) * 1616) * 2 + tg * 16;

    float acc[2][4];
#pragma unroll
    for (int nt = 0; nt < 2; nt++)
#pragma unroll
        for (int j = 0; j < 4; j++) acc[nt][j] = 0.f;

#pragma unroll
    for (int s = 0; s < 50; s++) {
        const int off = s >> 1;
        const int half = s & 1;
        const int dy = off / 5, dx = off - dy * 5;
        const uint32_t dpixB = (uint32_t)((dy * 11 + dx) * 80) * 2 + half * 64;
        const uint32_t wofsB = (uint32_t)(off * 128) + half * 64;
        uint4 w0 = lds128(w0B + wofsB);
        uint4 w1 = lds128(w1B + wofsB);
        uint4 u0 = lds128(a0B + dpixB);
        uint4 u1 = lds128(a1B + dpixB);
        mma_bf16(acc[0], u0.x, u1.x, u0.z, u1.z, w0.x, w0.z);
        mma_bf16(acc[1], u0.x, u1.x, u0.z, u1.z, w1.x, w1.z);
        mma_bf16(acc[0], u0.x, u1.x, u0.z, u1.z, w0.y, w0.w);
        mma_bf16(acc[1], u0.x, u1.x, u0.z, u1.z, w1.y, w1.w);
        mma_bf16(acc[0], u0.y, u1.y, u0.w, u1.w, w0.x, w0.z);
        mma_bf16(acc[1], u0.y, u1.y, u0.w, u1.w, w1.x, w1.z);
    }

    // epilogue: bias + relu, pool (pad=1)
    {
        bool v0 = (r0 < 147) && (img0 + i0 < BATCH);
        bool v1 = (r1 < 147) && (img0 + i1 < BATCH);
        int pi0 = i0 * 256 + (((y0 + 1) >> 1) * 4 + ((x0 + 1) >> 1)) * 16;
        int pi1 = i1 * 256 + (((y1 + 1) >> 1) * 4 + ((x1 + 1) >> 1)) * 16;
#pragma unroll
        for (int nt = 0; nt < 2; nt++) {
            int col = nt * 8 + tg * 2;
            float bb0 = s_bias[col], bb1 = s_bias[col + 1];
            if (v0) {
                atomicMax(&s_pool[pi0 + col], __float_as_int(fmaxf(acc[nt][0] + bb0, 0.f)));
                atomicMax(&s_pool[pi0 + col + 1], __float_as_int(fmaxf(acc[nt][1] + bb1, 0.f)));
            }
            if (v1) {
                atomicMax(&s_pool[pi1 + col], __float_as_int(fmaxf(acc[nt][2] + bb0, 0.f)));
                atomicMax(&s_pool[pi1 + col + 1], __float_as_int(fmaxf(acc[nt][3] + bb1, 0.f)));
            }
        }
    }
    __syncthreads();
    // g_a3 keeps STANDARD interleave (fc1 convention)
    for (int i = tid; i < 384; i += 320) {
        int img = i >> 7, r = i & 127;
        if (img0 + img < BATCH) {
            int ocl = r >> 3, pp = r & 7;
            float v0 = __int_as_float(s_pool[img * 256 + (2 * pp) * 16 + ocl]);
            float v1 = __int_as_float(s_pool[img * 256 + (2 * pp + 1) * 16 + ocl]);
            int gp = (g * 16 + ocl) * 8 + pp;
            *reinterpret_cast<uint2*>(g_a3 + (img0 + img) * 2048 + gp * 4) = pack4(v0, v1);
        }
    }
}

// ---------------- fc1 via bf16x3 MMA, cp.async double-buffered ----------------
#define FC1_STRIDE 144
#define FC1_STAGE (128 * FC1_STRIDE)
#define FC1_SMEM (4 * FC1_STAGE * 2)
__global__ void __launch_bounds__(256) k_fc1(const float* __restrict__ bias) {
    extern __shared__ char smem[];
    __nv_bfloat16* s_base = (__nv_bfloat16*)smem;
    const int tid = threadIdx.x;
    const int warp = tid >> 5, lane = tid & 31;
    const int wm = warp >> 1, wn = warp & 1;
    const int m0 = blockIdx.y * 128, n0 = blockIdx.x * 128;
    const int gid = lane >> 2, tg = lane & 3;
    const int kq = tg * 4;

    float acc[2][8][4];
#pragma unroll
    for (int mt = 0; mt < 2; mt++)
#pragma unroll
        for (int nt = 0; nt < 8; nt++)
#pragma unroll
            for (int j = 0; j < 4; j++) acc[mt][nt][j] = 0.f;

    auto load_stage = [&](int stage, int k0e) {
        __nv_bfloat16* s_a = s_base + stage * 2 * FC1_STAGE;
        __nv_bfloat16* s_b = s_a + FC1_STAGE;
        for (int i = tid; i < 4096; i += 256) {
            int j = i & 2047;
            int row = j >> 4, q = j & 15;
            int dst = row * FC1_STRIDE + q * 8;
            if (i < 2048)
                cp16(s_a + dst, g_a3 + (m0 + row) * 2048 + k0e + q * 8);
            else
                cp16(s_b + dst, g_fw1 + (n0 + row) * 2048 + k0e + q * 8);
        }
        CP_COMMIT();
    };

    load_stage(0, 0);

    const uint32_t sB = smem_u32(s_base);
    uint32_t arowB[2], browB[8];
#pragma unroll
    for (int mt = 0; mt < 2; mt++)
        arowB[mt] = (uint32_t)((wm * 32 + mt * 16 + gid) * FC1_STRIDE + kq) * 2;
#pragma unroll
    for (int nt = 0; nt < 8; nt++)
        browB[nt] = (uint32_t)((wn * 64 + nt * 8 + gid) * FC1_STRIDE + kq) * 2 + (uint32_t)(FC1_STAGE * 2);

#pragma unroll 1
    for (int k = 0; k < 16; k++) {
        if (k < 15) load_stage((k + 1) & 1, (k + 1) * 128);
        if (k < 15) { CP_WAIT(1); } else { CP_WAIT(0); }
        __syncthreads();
        const uint32_t stB = sB + (uint32_t)((k & 1) * 2 * FC1_STAGE * 2);
#pragma unroll
        for (int ks = 0; ks < 4; ks++) {
            const uint32_t kbB = (uint32_t)(ks * 32) * 2;
            uint32_t ah[2][4], al[2][4];
#pragma unroll
            for (int mt = 0; mt < 2; mt++) {
                uint32_t base = stB + arowB[mt] + kbB;
                uint2 q0 = lds64(base);
                uint2 q1 = lds64(base + 8 * FC1_STRIDE * 2);
                uint2 q2 = lds64(base + 32);
                uint2 q3 = lds64(base + 8 * FC1_STRIDE * 2 + 32);
                ah[mt][0] = q0.x; al[mt][0] = q0.y;
                ah[mt][1] = q1.x; al[mt][1] = q1.y;
                ah[mt][2] = q2.x; al[mt][2] = q2.y;
                ah[mt][3] = q3.x; al[mt][3] = q3.y;
            }
            uint32_t bh[8][2], bl[8][2];
#pragma unroll
            for (int nt = 0; nt < 8; nt++) {
                uint32_t base = stB + browB[nt] + kbB;
                uint2 w0 = lds64(base);
                uint2 w1 = lds64(base + 32);
                bh[nt][0] = w0.x; bl[nt][0] = w0.y;
                bh[nt][1] = w1.x; bl[nt][1] = w1.y;
            }
#pragma unroll
            for (int mt = 0; mt < 2; mt++) {
#pragma unroll
                for (int nt = 0; nt < 8; nt++)
                    mma_bf16(acc[mt][nt], ah[mt][0], ah[mt][1], ah[mt][2], ah[mt][3], bh[nt][0], bh[nt][1]);
#pragma unroll
                for (int nt = 0; nt < 8; nt++)
                    mma_bf16(acc[mt][nt], ah[mt][0], ah[mt][1], ah[mt][2], ah[mt][3], bl[nt][0], bl[nt][1]);
#pragma unroll
                for (int nt = 0; nt < 8; nt++)
                    mma_bf16(acc[mt][nt], al[mt][0], al[mt][1], al[mt][2], al[mt][3], bh[nt][0], bh[nt][1]);
            }
        }
        __syncthreads();
    }
#pragma unroll
    for (int mt = 0; mt < 2; mt++) {
        int r = m0 + wm * 32 + mt * 16 + gid;
#pragma unroll
        for (int nt = 0; nt < 8; nt++) {
            int c = n0 + wn * 64 + nt * 8 + tg * 2;
            float b0 = bias[c], b1 = bias[c + 1];
            g_a4[r * 256 + c]           = fmaxf(acc[mt][nt][0] + b0, 0.f);
            g_a4[r * 256 + c + 1]       = fmaxf(acc[mt][nt][1] + b1, 0.f);
            g_a4[(r + 8) * 256 + c]     = fmaxf(acc[mt][nt][2] + b0, 0.f);
            g_a4[(r + 8) * 256 + c + 1] = fmaxf(acc[mt][nt][3] + b1, 0.f);
        }
    }
}

// ---------------- fc2 + log_softmax ----------------
__global__ void __launch_bounds__(256) k_fc2(const float* __restrict__ W,
                                             const float* __restrict__ bias,
                                             float* __restrict__ out) {
    __shared__ float s_w[2560];
    __shared__ float s_b[10];
    const int tid = threadIdx.x;
    for (int i = tid; i < 2560; i += 256) s_w[i] = W[i];
    if (tid < 10) s_b[tid] = bias[tid];
    __syncthreads();

    const int warp = tid >> 5, lane = tid & 31;
    const int row = blockIdx.x * 8 + warp;
    float hv[8];
    const float* hp = g_a4 + row * 256 + lane;
#pragma unroll
    for (int j = 0; j < 8; j++) hv[j] = hp[j * 32];

    float acc[10];
#pragma unroll
    for (int o = 0; o < 10; o++) acc[o] = 0.f;
#pragma unroll
    for (int j = 0; j < 8; j++) {
#pragma unroll
        for (int o = 0; o < 10; o++)
            acc[o] += hv[j] * s_w[o * 256 + lane + j * 32];
    }
#pragma unroll
    for (int o = 0; o < 10; o++) {
#pragma unroll
        for (int off = 16; off > 0; off >>= 1)
            acc[o] += __shfl_xor_sync(0xffffffffu, acc[o], off);
    }
    if (lane == 0) {
        float l[10], m = -1e30f;
#pragma unroll
        for (int o = 0; o < 10; o++) { l[o] = acc[o] + s_b[o]; m = fmaxf(m, l[o]); }
        float s = 0.f;
#pragma unroll
        for (int o = 0; o < 10; o++) s += expf(l[o] - m);
        float ls = logf(s);
        float* op = out + row * 10;
#pragma unroll
        for (int o = 0; o < 10; o++) op[o] = l[o] - m - ls;
    }
}

extern "C" void kernel_launch(void* const* d_in, const int* in_sizes, int n_in,
                              void* d_out, int out_size) {
    const float* x   = (const float*)d_in[0];
    const float* w1  = (const float*)d_in[1];
    const float* b1  = (const float*)d_in[2];
    const float* w2  = (const float*)d_in[3];
    const float* b2  = (const float*)d_in[4];
    const float* w3  = (const float*)d_in[5];
    const float* b3  = (const float*)d_in[6];
    const float* fw1 = (const float*)d_in[7];
    const float* fb1 = (const float*)d_in[8];
    const float* fw2 = (const float*)d_in[9];
    const float* fb2 = (const float*)d_in[10];
    float* out = (float*)d_out;

    cudaFuncSetAttribute(k_conv1, cudaFuncAttributeMaxDynamicSharedMemorySize, C1_SMEM);
    cudaFuncSetAttribute(k_conv2, cudaFuncAttributeMaxDynamicSharedMemorySize, C2_SMEM);
    cudaFuncSetAttribute(k_conv3, cudaFuncAttributeMaxDynamicSharedMemorySize, C3_SMEM);
    cudaFuncSetAttribute(k_fc1,   cudaFuncAttributeMaxDynamicSharedMemorySize, FC1_SMEM);

    k_prep<<<512, 256>>>(fw1, w2, w3);
    k_conv1<<<BATCH / 4, 512, C1_SMEM>>>(x, w1, b1);
    k_conv2<<<BATCH / 4, 512, C2_SMEM>>>(b2);
    k_conv3<<<dim3((BATCH + 2) / 3, 4), 320, C3_SMEM>>>(b3);
    k_fc1<<<dim3(2, BATCH / 128), 256, FC1_SMEM>>>(fb1);
    k_fc2<<<BATCH / 8, 256>>>(fw2, fb2, out);
}

// round 16
// speedup vs baseline: 1.2539x; 1.2539x over previous
#include <cuda_runtime.h>
#include <cuda_bf16.h>
#include <math.h>
#include <stdint.h>

#define BATCH 8192

// Activations / weights in gmem, bf16 hi/lo interleaved in groups of 4:
//   group p (4 elems): [hi(2p), hi(2p+1), lo(2p), lo(2p+1)]
__device__ __nv_bfloat16 g_a1[BATCH * 196 * 32];   // conv1 out: [b][px][16ic -> 32 elem]
__device__ __nv_bfloat16 g_a2[BATCH * 49 * 64];    // conv2 out: [b][px][32ic -> 64 elem]
__device__ __nv_bfloat16 g_a3[BATCH * 2048];       // conv3 out: [b][1024k -> 2048 elem]
__device__ float g_a4[BATCH * 256];                // fc1 out
__device__ __nv_bfloat16 g_fw1[256 * 2048];        // fc1 W interleaved
__device__ __nv_bfloat16 g_w2i[32 * 800];          // conv2 W: [oc][off*32 + p*4]
__device__ __nv_bfloat16 g_w3i[64 * 1600];         // conv3 W: [oc][off*64 + p*4]

__device__ __forceinline__ uint16_t bfbits(__nv_bfloat16 x) {
    return *reinterpret_cast<uint16_t*>(&x);
}
__device__ __forceinline__ void bf16split(float v, __nv_bfloat16& h, __nv_bfloat16& l) {
    h = __float2bfloat16(v);
    l = __float2bfloat16(v - __bfloat162float(h));
}
__device__ __forceinline__ uint2 pack4(float v0, float v1) {
    __nv_bfloat16 h0, l0, h1, l1;
    bf16split(v0, h0, l0);
    bf16split(v1, h1, l1);
    uint2 r;
    r.x = (uint32_t)bfbits(h0) | ((uint32_t)bfbits(h1) << 16);
    r.y = (uint32_t)bfbits(l0) | ((uint32_t)bfbits(l1) << 16);
    return r;
}

// NON-volatile mma: deps fully expressed via register constraints; lets the
// scheduler interleave mmas with loads across the unrolled k-loops.
__device__ __forceinline__ void mma_bf16(float* c,
                                         uint32_t a0, uint32_t a1, uint32_t a2, uint32_t a3,
                                         uint32_t b0, uint32_t b1) {
    asm("mma.sync.aligned.m16n8k16.row.col.f32.bf16.bf16.f32 "
        "{%0,%1,%2,%3}, {%4,%5,%6,%7}, {%8,%9}, {%0,%1,%2,%3};"
        : "+f"(c[0]), "+f"(c[1]), "+f"(c[2]), "+f"(c[3])
        : "r"(a0), "r"(a1), "r"(a2), "r"(a3), "r"(b0), "r"(b1));
}

__device__ __forceinline__ uint2 lds_u64(const __nv_bfloat16* p, int elem_idx) {
    return *reinterpret_cast<const uint2*>(p + elem_idx);
}
__device__ __forceinline__ uint32_t lds_u16e(const __nv_bfloat16* p, int elem_idx) {
    return (uint32_t)*reinterpret_cast<const uint16_t*>(p + elem_idx);
}
__device__ __forceinline__ uint32_t pk(uint32_t lo, uint32_t hi) {
    return lo | (hi << 16);
}

// cp.async helpers (16B)
__device__ __forceinline__ void cp16(void* smem_dst, const void* gmem_src) {
    uint32_t d = (uint32_t)__cvta_generic_to_shared(smem_dst);
    asm volatile("cp.async.cg.shared.global [%0], [%1], 16;\n" :: "r"(d), "l"(gmem_src));
}
#define CP_COMMIT() asm volatile("cp.async.commit_group;\n" ::: "memory")
#define CP_WAIT(n)  asm volatile("cp.async.wait_group %0;\n" :: "n"(n) : "memory")

// ---------------- merged prep kernel ----------------
__global__ void __launch_bounds__(256) k_prep(const float* __restrict__ fw1,
                                              const float* __restrict__ w2,
                                              const float* __restrict__ w3) {
    int i = blockIdx.x * 256 + threadIdx.x;   // 131072 total
    {
        int row = i >> 9, p = i & 511;
        uint2 v = pack4(fw1[row * 1024 + 2 * p], fw1[row * 1024 + 2 * p + 1]);
        *reinterpret_cast<uint2*>(g_fw1 + row * 2048 + p * 4) = v;
    }
    if (i < 6400) {
        int oc = i / 200, r = i - oc * 200;
        int off = r >> 3, p = r & 7;
        uint2 v = pack4(w2[oc * 400 + (2 * p) * 25 + off], w2[oc * 400 + (2 * p + 1) * 25 + off]);
        *reinterpret_cast<uint2*>(g_w2i + oc * 800 + off * 32 + p * 4) = v;
    }
    if (i < 25600) {
        int oc = i / 400, r = i - oc * 400;
        int off = r >> 4, p = r & 15;
        uint2 v = pack4(w3[oc * 800 + (2 * p) * 25 + off], w3[oc * 800 + (2 * p + 1) * 25 + off]);
        *reinterpret_cast<uint2*>(g_w3i + oc * 1600 + off * 64 + p * 4) = v;
    }
}

// ---------------- conv1 (1->16) via bf16x3 MMA, weights-as-A ----------------
#define C1_SMEM 70496
__global__ void __launch_bounds__(512) k_conv1(const float* __restrict__ x,
                                               const float* __restrict__ w1,
                                               const float* __restrict__ b1) {
    extern __shared__ char smem[];
    __nv_bfloat16* s_hi = (__nv_bfloat16*)(smem);            // 4488 elem (4 x 34x33)
    __nv_bfloat16* s_lo = (__nv_bfloat16*)(smem + 8976);     // 4488 elem
    __nv_bfloat16* s_w  = (__nv_bfloat16*)(smem + 17952);    // 16 x 72 elem interleaved
    int*           s_pool = (int*)(smem + 20256);            // 4*196*16
    float*         s_bias = (float*)(smem + 70432);

    const int img0 = blockIdx.x * 4;
    const int tid = threadIdx.x;
    const int warp = tid >> 5;
    const int lane = tid & 31;
    const int gid = lane >> 2;
    const int tg  = lane & 3;

    for (int i = tid; i < 4488; i += 512) ((uint32_t*)smem)[i] = 0u;
    for (int i = tid; i < 12544; i += 512) s_pool[i] = 0;
    if (tid < 16) s_bias[tid] = b1[tid];
    if (tid < 256) {
        int oc = tid >> 4, p = tid & 15;
        int k0 = 2 * p, k1 = 2 * p + 1;
        float v0 = (k0 < 25) ? w1[oc * 25 + k0] : 0.f;
        float v1 = (k1 < 25) ? w1[oc * 25 + k1] : 0.f;
        *reinterpret_cast<uint2*>(s_w + oc * 72 + p * 4) = pack4(v0, v1);
    }
    __syncthreads();
    for (int i = tid; i < 3136; i += 512) {
        int img = i / 784, px = i - img * 784;
        int iy = px / 28, ix = px - iy * 28;
        __nv_bfloat16 h, l;
        bf16split(x[(img0 + img) * 784 + px], h, l);
        int d = img * 1122 + (iy + 2) * 33 + (ix + 2);
        s_hi[d] = h; s_lo[d] = l;
    }
    __syncthreads();

    uint32_t Ah[2][4], Al[2][4];
#pragma unroll
    for (int s = 0; s < 2; s++) {
        uint2 g0 = lds_u64(s_w, gid * 72 + (tg + 8 * s) * 4);
        uint2 g1 = lds_u64(s_w, (gid + 8) * 72 + (tg + 8 * s) * 4);
        uint2 g2 = lds_u64(s_w, gid * 72 + (tg + 4 + 8 * s) * 4);
        uint2 g3 = lds_u64(s_w, (gid + 8) * 72 + (tg + 4 + 8 * s) * 4);
        Ah[s][0] = g0.x; Al[s][0] = g0.y;
        Ah[s][1] = g1.x; Al[s][1] = g1.y;
        Ah[s][2] = g2.x; Al[s][2] = g2.y;
        Ah[s][3] = g3.x; Al[s][3] = g3.y;
    }

    int doff[8];
    {
        int kk[8] = {2 * tg, 2 * tg + 1, 2 * tg + 8, 2 * tg + 9,
                     2 * tg + 16, 2 * tg + 17, 2 * tg + 24, 2 * tg + 25};
#pragma unroll
        for (int j = 0; j < 8; j++) {
            int ky = kk[j] / 5, kx = kk[j] - ky * 5;
            doff[j] = ky * 33 + kx;
        }
    }

    const float bb0 = s_bias[gid], bb1 = s_bias[gid + 8];

#pragma unroll 1
    for (int ti = 0; ti < 13; ti++) {
#pragma unroll
        for (int half = 0; half < 2; half++) {
            int t = warp + 16 * (2 * ti + half);
            if (t < 392) {
                int img = t / 98, tb = t - img * 98;
                int pxg = tb * 8 + gid;
                int yg = pxg / 28, xg = pxg - yg * 28;
                int ab = img * 1122 + yg * 33 + xg;

                uint32_t bh0 = pk(lds_u16e(s_hi, ab + doff[0]), lds_u16e(s_hi, ab + doff[1]));
                uint32_t bh1 = pk(lds_u16e(s_hi, ab + doff[2]), lds_u16e(s_hi, ab + doff[3]));
                uint32_t bh2 = pk(lds_u16e(s_hi, ab + doff[4]), lds_u16e(s_hi, ab + doff[5]));
                uint32_t bh3 = pk(lds_u16e(s_hi, ab + doff[6]), lds_u16e(s_hi, ab + doff[7]));
                uint32_t bl0 = pk(lds_u16e(s_lo, ab + doff[0]), lds_u16e(s_lo, ab + doff[1]));
                uint32_t bl1 = pk(lds_u16e(s_lo, ab + doff[2]), lds_u16e(s_lo, ab + doff[3]));
                uint32_t bl2 = pk(lds_u16e(s_lo, ab + doff[4]), lds_u16e(s_lo, ab + doff[5]));
                uint32_t bl3 = pk(lds_u16e(s_lo, ab + doff[6]), lds_u16e(s_lo, ab + doff[7]));

                float c[4] = {0.f, 0.f, 0.f, 0.f};
                mma_bf16(c, Ah[0][0], Ah[0][1], Ah[0][2], Ah[0][3], bh0, bh1);
                mma_bf16(c, Ah[1][0], Ah[1][1], Ah[1][2], Ah[1][3], bh2, bh3);
                mma_bf16(c, Ah[0][0], Ah[0][1], Ah[0][2], Ah[0][3], bl0, bl1);
                mma_bf16(c, Ah[1][0], Ah[1][1], Ah[1][2], Ah[1][3], bl2, bl3);
                mma_bf16(c, Al[0][0], Al[0][1], Al[0][2], Al[0][3], bh0, bh1);
                mma_bf16(c, Al[1][0], Al[1][1], Al[1][2], Al[1][3], bh2, bh3);

                int pxo = tb * 8 + 2 * tg;
                int yo = pxo / 28, xo = pxo - yo * 28;
                int sp = (yo >> 1) * 14 + (xo >> 1);
                float v0 = fmaxf(c[0] + bb0, 0.f);
                float v1 = fmaxf(c[1] + bb0, 0.f);
                float v2 = fmaxf(c[2] + bb1, 0.f);
                float v3 = fmaxf(c[3] + bb1, 0.f);
                atomicMax(&s_pool[img * 3136 + sp * 16 + gid], __float_as_int(fmaxf(v0, v1)));
                atomicMax(&s_pool[img * 3136 + sp * 16 + gid + 8], __float_as_int(fmaxf(v2, v3)));
            }
        }
    }
    __syncthreads();
    for (int i = tid; i < 6272; i += 512) {
        int img = i / 1568, rr = i - img * 1568;
        int sp = rr >> 3, p = rr & 7;
        float v0 = __int_as_float(s_pool[img * 3136 + sp * 16 + 2 * p]);
        float v1 = __int_as_float(s_pool[img * 3136 + sp * 16 + 2 * p + 1]);
        *reinterpret_cast<uint2*>(g_a1 + ((img0 + img) * 196 + sp) * 32 + p * 4) = pack4(v0, v1);
    }
}

// ---------------- conv2 (16->32): 4 img/block, 512 thr, full unroll ----------------
#define C2_SMEM 201984
__global__ void __launch_bounds__(512) k_conv2(const float* __restrict__ b2) {
    extern __shared__ char smem[];
    __nv_bfloat16* s_in = (__nv_bfloat16*)(smem);               // 62208 elem
    __nv_bfloat16* s_w  = (__nv_bfloat16*)(smem + 124416);      // 26112 elem
    int*           s_pool = (int*)(smem + 176640);              // 6272 int
    float*         s_bias = (float*)(smem + 201728);

    const int img0 = blockIdx.x * 4;
    const int tid = threadIdx.x;
    const int warp = tid >> 5;
    const int lane = tid & 31;
    const int gid = lane >> 2;
    const int tg  = lane & 3;
    const int kq  = tg * 4;

    uint4 z4 = {0, 0, 0, 0};
    for (int i = tid; i < 7776; i += 512) ((uint4*)s_in)[i] = z4;
    for (int i = tid; i < 6272; i += 512) s_pool[i] = 0;
    if (tid < 32) s_bias[tid] = b2[tid];
    __syncthreads();
    for (int i = tid; i < 3200; i += 512) {
        int oc = i / 100, r = i - oc * 100;
        cp16(s_w + oc * 816 + r * 8, g_w2i + oc * 800 + r * 8);
    }
    for (int i = tid; i < 3136; i += 512) {
        int img = i / 784, r = i - img * 784;
        int px = r >> 2, q = r & 3;
        int y = px / 14, xx = px - y * 14;
        cp16(s_in + img * 15552 + ((y + 2) * 18 + (xx + 2)) * 48 + q * 8,
             g_a1 + ((img0 + img) * 196 + px) * 32 + q * 8);
    }
    CP_COMMIT();
    CP_WAIT(0);
    __syncthreads();

    int aoff0[4], aoff1[4];
#pragma unroll
    for (int ti = 0; ti < 4; ti++) {
        int t = warp + 16 * ti;
        if (t < 49) {
            int r0 = t * 16 + gid, r1 = r0 + 8;
            int i0 = r0 / 196, p0 = r0 - i0 * 196;
            int i1 = r1 / 196, p1 = r1 - i1 * 196;
            int y0 = p0 / 14, x0 = p0 - y0 * 14;
            int y1 = p1 / 14, x1 = p1 - y1 * 14;
            aoff0[ti] = i0 * 15552 + (y0 * 18 + x0) * 48 + kq;
            aoff1[ti] = i1 * 15552 + (y1 * 18 + x1) * 48 + kq;
        }
    }

    float acc[4][4][4];
#pragma unroll
    for (int ti = 0; ti < 4; ti++)
#pragma unroll
        for (int nt = 0; nt < 4; nt++)
#pragma unroll
            for (int j = 0; j < 4; j++) acc[ti][nt][j] = 0.f;

    int wrb[4];
#pragma unroll
    for (int nt = 0; nt < 4; nt++) wrb[nt] = (nt * 8 + gid) * 816 + kq;

#pragma unroll
    for (int off = 0; off < 25; off++) {
        const int dy = off / 5, dx = off - dy * 5;       // compile-time after unroll
        const int dpix = (dy * 18 + dx) * 48;
        const int wofs = off * 32;
        uint32_t bh0[4], bh1[4], bl0[4], bl1[4];
#pragma unroll
        for (int nt = 0; nt < 4; nt++) {
            uint2 w0 = lds_u64(s_w, wrb[nt] + wofs);
            uint2 w1 = lds_u64(s_w, wrb[nt] + wofs + 16);
            bh0[nt] = w0.x; bl0[nt] = w0.y;
            bh1[nt] = w1.x; bl1[nt] = w1.y;
        }
#pragma unroll
        for (int ti = 0; ti < 4; ti++) {
            int t = warp + 16 * ti;
            if (t < 49) {
                int o0 = aoff0[ti] + dpix;
                int o1 = aoff1[ti] + dpix;
                uint2 a00 = lds_u64(s_in, o0);
                uint2 a01 = lds_u64(s_in, o1);
                uint2 a02 = lds_u64(s_in, o0 + 16);
                uint2 a03 = lds_u64(s_in, o1 + 16);
#pragma unroll
                for (int nt = 0; nt < 4; nt++)
                    mma_bf16(acc[ti][nt], a00.x, a01.x, a02.x, a03.x, bh0[nt], bh1[nt]);
#pragma unroll
                for (int nt = 0; nt < 4; nt++)
                    mma_bf16(acc[ti][nt], a00.x, a01.x, a02.x, a03.x, bl0[nt], bl1[nt]);
#pragma unroll
                for (int nt = 0; nt < 4; nt++)
                    mma_bf16(acc[ti][nt], a00.y, a01.y, a02.y, a03.y, bh0[nt], bh1[nt]);
            }
        }
    }

#pragma unroll
    for (int ti = 0; ti < 4; ti++) {
        int t = warp + 16 * ti;
        if (t < 49) {
            int r0 = t * 16 + gid, r1 = r0 + 8;
            int i0 = r0 / 196, p0 = r0 - i0 * 196;
            int i1 = r1 / 196, p1 = r1 - i1 * 196;
            int y0 = p0 / 14, x0 = p0 - y0 * 14;
            int y1 = p1 / 14, x1 = p1 - y1 * 14;
            int pi0 = i0 * 1568 + ((y0 >> 1) * 7 + (x0 >> 1)) * 32;
            int pi1 = i1 * 1568 + ((y1 >> 1) * 7 + (x1 >> 1)) * 32;
#pragma unroll
            for (int nt = 0; nt < 4; nt++) {
                int col = nt * 8 + tg * 2;
                float bb0 = s_bias[col], bb1 = s_bias[col + 1];
                float v0 = fmaxf(acc[ti][nt][0] + bb0, 0.f);
                float v1 = fmaxf(acc[ti][nt][1] + bb1, 0.f);
                float v2 = fmaxf(acc[ti][nt][2] + bb0, 0.f);
                float v3 = fmaxf(acc[ti][nt][3] + bb1, 0.f);
                float q0 = __shfl_xor_sync(0xffffffffu, v0, 4);
                float q1 = __shfl_xor_sync(0xffffffffu, v1, 4);
                float q2 = __shfl_xor_sync(0xffffffffu, v2, 4);
                float q3 = __shfl_xor_sync(0xffffffffu, v3, 4);
                if ((gid & 1) == 0) {
                    atomicMax(&s_pool[pi0 + col], __float_as_int(fmaxf(v0, q0)));
                    atomicMax(&s_pool[pi0 + col + 1], __float_as_int(fmaxf(v1, q1)));
                    atomicMax(&s_pool[pi1 + col], __float_as_int(fmaxf(v2, q2)));
                    atomicMax(&s_pool[pi1 + col + 1], __float_as_int(fmaxf(v3, q3)));
                }
            }
        }
    }
    __syncthreads();
    for (int i = tid; i < 3136; i += 512) {
        int img = i / 784, r = i - img * 784;
        int px = r >> 4, p = r & 15;
        float v0 = __int_as_float(s_pool[img * 1568 + px * 32 + 2 * p]);
        float v1 = __int_as_float(s_pool[img * 1568 + px * 32 + 2 * p + 1]);
        *reinterpret_cast<uint2*>(g_a2 + ((img0 + img) * 49 + px) * 64 + p * 4) = pack4(v0, v1);
    }
}

// ---------------- conv3 (32->64): 3 img x 16-oc, 320 thr, full unroll ----------------
#define C3_SMEM 113056
__global__ void __launch_bounds__(320) k_conv3(const float* __restrict__ b3) {
    extern __shared__ char smem[];
    __nv_bfloat16* s_in = (__nv_bfloat16*)(smem);               // 29040 elem
    __nv_bfloat16* s_w  = (__nv_bfloat16*)(smem + 58080);       // 25856 elem
    int*           s_pool = (int*)(smem + 109792);              // 768 int
    float*         s_bias = (float*)(smem + 112864);            // 16

    const int img0 = blockIdx.x * 3;
    const int g = blockIdx.y;        // oc-group 0..3 (16 oc each)
    const int tid = threadIdx.x;
    const int warp = tid >> 5;       // 0..9 -> m-tile
    const int lane = tid & 31;
    const int gid = lane >> 2;
    const int tg  = lane & 3;
    const int kq  = tg * 4;

    uint4 z4 = {0, 0, 0, 0};
    for (int i = tid; i < 3630; i += 320) ((uint4*)s_in)[i] = z4;
    for (int i = tid; i < 768; i += 320) s_pool[i] = 0;
    if (tid < 16) s_bias[tid] = b3[g * 16 + tid];
    __syncthreads();
    const __nv_bfloat16* wg = g_w3i + g * 16 * 1600;
    for (int i = tid; i < 3200; i += 320) {
        int ocl = i / 200, r = i - ocl * 200;
        cp16(s_w + ocl * 1616 + r * 8, wg + ocl * 1600 + r * 8);
    }
    for (int i = tid; i < 1176; i += 320) {
        int img = i / 392, r = i - img * 392;
        if (img0 + img < BATCH) {
            int px = r >> 3, q = r & 7;
            int y = px / 7, xx = px - y * 7;
            cp16(s_in + img * 9680 + ((y + 2) * 11 + (xx + 2)) * 80 + q * 8,
                 g_a2 + ((img0 + img) * 49 + px) * 64 + q * 8);
        }
    }
    CP_COMMIT();
    CP_WAIT(0);
    __syncthreads();

    int r0 = warp * 16 + gid, r1 = r0 + 8;
    int rc0 = r0 < 146 ? r0 : 146;
    int rc1 = r1 < 146 ? r1 : 146;
    int i0 = rc0 / 49, p0 = rc0 - i0 * 49;
    int i1 = rc1 / 49, p1 = rc1 - i1 * 49;
    int y0 = p0 / 7, x0 = p0 - y0 * 7;
    int y1 = p1 / 7, x1 = p1 - y1 * 7;
    const int aoff0 = i0 * 9680 + (y0 * 11 + x0) * 80 + kq;
    const int aoff1 = i1 * 9680 + (y1 * 11 + x1) * 80 + kq;
    const int wb0 = gid * 1616 + kq;
    const int wb1 = (8 + gid) * 1616 + kq;

    float acc[2][4];
#pragma unroll
    for (int nt = 0; nt < 2; nt++)
#pragma unroll
        for (int j = 0; j < 4; j++) acc[nt][j] = 0.f;

#pragma unroll
    for (int s = 0; s < 50; s++) {
        const int off = s >> 1;
        const int iche = (s & 1) << 5;
        const int dy = off / 5, dx = off - dy * 5;      // compile-time after unroll
        const int dpix = (dy * 11 + dx) * 80 + iche;
        const int wofs = off * 64 + iche;
        uint2 w00 = lds_u64(s_w, wb0 + wofs);
        uint2 w01 = lds_u64(s_w, wb0 + wofs + 16);
        uint2 w10 = lds_u64(s_w, wb1 + wofs);
        uint2 w11 = lds_u64(s_w, wb1 + wofs + 16);
        int o0 = aoff0 + dpix;
        int o1 = aoff1 + dpix;
        uint2 a00 = lds_u64(s_in, o0);
        uint2 a01 = lds_u64(s_in, o1);
        uint2 a02 = lds_u64(s_in, o0 + 16);
        uint2 a03 = lds_u64(s_in, o1 + 16);
        mma_bf16(acc[0], a00.x, a01.x, a02.x, a03.x, w00.x, w01.x);
        mma_bf16(acc[1], a00.x, a01.x, a02.x, a03.x, w10.x, w11.x);
        mma_bf16(acc[0], a00.x, a01.x, a02.x, a03.x, w00.y, w01.y);
        mma_bf16(acc[1], a00.x, a01.x, a02.x, a03.x, w10.y, w11.y);
        mma_bf16(acc[0], a00.y, a01.y, a02.y, a03.y, w00.x, w01.x);
        mma_bf16(acc[1], a00.y, a01.y, a02.y, a03.y, w10.x, w11.x);
    }

    // epilogue: bias + relu, pool (pad=1)
    {
        bool v0 = (r0 < 147) && (img0 + i0 < BATCH);
        bool v1 = (r1 < 147) && (img0 + i1 < BATCH);
        int pi0 = i0 * 256 + (((y0 + 1) >> 1) * 4 + ((x0 + 1) >> 1)) * 16;
        int pi1 = i1 * 256 + (((y1 + 1) >> 1) * 4 + ((x1 + 1) >> 1)) * 16;
#pragma unroll
        for (int nt = 0; nt < 2; nt++) {
            int col = nt * 8 + tg * 2;
            float bb0 = s_bias[col], bb1 = s_bias[col + 1];
            if (v0) {
                atomicMax(&s_pool[pi0 + col], __float_as_int(fmaxf(acc[nt][0] + bb0, 0.f)));
                atomicMax(&s_pool[pi0 + col + 1], __float_as_int(fmaxf(acc[nt][1] + bb1, 0.f)));
            }
            if (v1) {
                atomicMax(&s_pool[pi1 + col], __float_as_int(fmaxf(acc[nt][2] + bb0, 0.f)));
                atomicMax(&s_pool[pi1 + col + 1], __float_as_int(fmaxf(acc[nt][3] + bb1, 0.f)));
            }
        }
    }
    __syncthreads();
    for (int i = tid; i < 384; i += 320) {
        int img = i >> 7, r = i & 127;
        if (img0 + img < BATCH) {
            int ocl = r >> 3, pp = r & 7;
            float v0 = __int_as_float(s_pool[img * 256 + (2 * pp) * 16 + ocl]);
            float v1 = __int_as_float(s_pool[img * 256 + (2 * pp + 1) * 16 + ocl]);
            int gp = (g * 16 + ocl) * 8 + pp;
            *reinterpret_cast<uint2*>(g_a3 + (img0 + img) * 2048 + gp * 4) = pack4(v0, v1);
        }
    }
}

// ---------------- fc1 via bf16x3 MMA, cp.async double-buffered ----------------
#define FC1_STRIDE 144
#define FC1_STAGE (128 * FC1_STRIDE)
#define FC1_SMEM (4 * FC1_STAGE * 2)
__global__ void __launch_bounds__(256) k_fc1(const float* __restrict__ bias) {
    extern __shared__ char smem[];
    __nv_bfloat16* s_base = (__nv_bfloat16*)smem;
    const int tid = threadIdx.x;
    const int warp = tid >> 5, lane = tid & 31;
    const int wm = warp >> 1, wn = warp & 1;
    const int m0 = blockIdx.y * 128, n0 = blockIdx.x * 128;
    const int gid = lane >> 2, tg = lane & 3;
    const int kq = tg * 4;

    float acc[2][8][4];
#pragma unroll
    for (int mt = 0; mt < 2; mt++)
#pragma unroll
        for (int nt = 0; nt < 8; nt++)
#pragma unroll
            for (int j = 0; j < 4; j++) acc[mt][nt][j] = 0.f;

    auto load_stage = [&](int stage, int k0e) {
        __nv_bfloat16* s_a = s_base + stage * 2 * FC1_STAGE;
        __nv_bfloat16* s_b = s_a + FC1_STAGE;
        for (int i = tid; i < 4096; i += 256) {
            int j = i & 2047;
            int row = j >> 4, q = j & 15;
            int dst = row * FC1_STRIDE + q * 8;
            if (i < 2048)
                cp16(s_a + dst, g_a3 + (m0 + row) * 2048 + k0e + q * 8);
            else
                cp16(s_b + dst, g_fw1 + (n0 + row) * 2048 + k0e + q * 8);
        }
        CP_COMMIT();
    };

    load_stage(0, 0);

#pragma unroll 1
    for (int k = 0; k < 16; k++) {
        if (k < 15) load_stage((k + 1) & 1, (k + 1) * 128);
        if (k < 15) { CP_WAIT(1); } else { CP_WAIT(0); }
        __syncthreads();
        __nv_bfloat16* s_a = s_base + (k & 1) * 2 * FC1_STAGE;
        __nv_bfloat16* s_b = s_a + FC1_STAGE;
#pragma unroll
        for (int ks = 0; ks < 4; ks++) {
            int kb = ks * 32 + kq;
            uint32_t ah[2][4], al[2][4];
#pragma unroll
            for (int mt = 0; mt < 2; mt++) {
                int base = (wm * 32 + mt * 16 + gid) * FC1_STRIDE + kb;
                uint2 q0 = lds_u64(s_a, base);
                uint2 q1 = lds_u64(s_a, base + 8 * FC1_STRIDE);
                uint2 q2 = lds_u64(s_a, base + 16);
                uint2 q3 = lds_u64(s_a, base + 8 * FC1_STRIDE + 16);
                ah[mt][0] = q0.x; al[mt][0] = q0.y;
                ah[mt][1] = q1.x; al[mt][1] = q1.y;
                ah[mt][2] = q2.x; al[mt][2] = q2.y;
                ah[mt][3] = q3.x; al[mt][3] = q3.y;
            }
            uint32_t bh[8][2], bl[8][2];
#pragma unroll
            for (int nt = 0; nt < 8; nt++) {
                int base = (wn * 64 + nt * 8 + gid) * FC1_STRIDE + kb;
                uint2 w0 = lds_u64(s_b, base);
                uint2 w1 = lds_u64(s_b, base + 16);
                bh[nt][0] = w0.x; bl[nt][0] = w0.y;
                bh[nt][1] = w1.x; bl[nt][1] = w1.y;
            }
#pragma unroll
            for (int mt = 0; mt < 2; mt++) {
#pragma unroll
                for (int nt = 0; nt < 8; nt++)
                    mma_bf16(acc[mt][nt], ah[mt][0], ah[mt][1], ah[mt][2], ah[mt][3], bh[nt][0], bh[nt][1]);
#pragma unroll
                for (int nt = 0; nt < 8; nt++)
                    mma_bf16(acc[mt][nt], ah[mt][0], ah[mt][1], ah[mt][2], ah[mt][3], bl[nt][0], bl[nt][1]);
#pragma unroll
                for (int nt = 0; nt < 8; nt++)
                    mma_bf16(acc[mt][nt], al[mt][0], al[mt][1], al[mt][2], al[mt][3], bh[nt][0], bh[nt][1]);
            }
        }
        __syncthreads();
    }
#pragma unroll
    for (int mt = 0; mt < 2; mt++) {
        int r = m0 + wm * 32 + mt * 16 + gid;
#pragma unroll
        for (int nt = 0; nt < 8; nt++) {
            int c = n0 + wn * 64 + nt * 8 + tg * 2;
            float b0 = bias[c], b1 = bias[c + 1];
            g_a4[r * 256 + c]           = fmaxf(acc[mt][nt][0] + b0, 0.f);
            g_a4[r * 256 + c + 1]       = fmaxf(acc[mt][nt][1] + b1, 0.f);
            g_a4[(r + 8) * 256 + c]     = fmaxf(acc[mt][nt][2] + b0, 0.f);
            g_a4[(r + 8) * 256 + c + 1] = fmaxf(acc[mt][nt][3] + b1, 0.f);
        }
    }
}

// ---------------- fc2 + log_softmax ----------------
__global__ void __launch_bounds__(256) k_fc2(const float* __restrict__ W,
                                             const float* __restrict__ bias,
                                             float* __restrict__ out) {
    __shared__ float s_w[2560];
    __shared__ float s_b[10];
    const int tid = threadIdx.x;
    for (int i = tid; i < 2560; i += 256) s_w[i] = W[i];
    if (tid < 10) s_b[tid] = bias[tid];
    __syncthreads();

    const int warp = tid >> 5, lane = tid & 31;
    const int row = blockIdx.x * 8 + warp;
    float hv[8];
    const float* hp = g_a4 + row * 256 + lane;
#pragma unroll
    for (int j = 0; j < 8; j++) hv[j] = hp[j * 32];

    float acc[10];
#pragma unroll
    for (int o = 0; o < 10; o++) acc[o] = 0.f;
#pragma unroll
    for (int j = 0; j < 8; j++) {
#pragma unroll
        for (int o = 0; o < 10; o++)
            acc[o] += hv[j] * s_w[o * 256 + lane + j * 32];
    }
#pragma unroll
    for (int o = 0; o < 10; o++) {
#pragma unroll
        for (int off = 16; off > 0; off >>= 1)
            acc[o] += __shfl_xor_sync(0xffffffffu, acc[o], off);
    }
    if (lane == 0) {
        float l[10], m = -1e30f;
#pragma unroll
        for (int o = 0; o < 10; o++) { l[o] = acc[o] + s_b[o]; m = fmaxf(m, l[o]); }
        float s = 0.f;
#pragma unroll
        for (int o = 0; o < 10; o++) s += expf(l[o] - m);
        float ls = logf(s);
        float* op = out + row * 10;
#pragma unroll
        for (int o = 0; o < 10; o++) op[o] = l[o] - m - ls;
    }
}

extern "C" void kernel_launch(void* const* d_in, const int* in_sizes, int n_in,
                              void* d_out, int out_size) {
    const float* x   = (const float*)d_in[0];
    const float* w1  = (const float*)d_in[1];
    const float* b1  = (const float*)d_in[2];
    const float* w2  = (const float*)d_in[3];
    const float* b2  = (const float*)d_in[4];
    const float* w3  = (const float*)d_in[5];
    const float* b3  = (const float*)d_in[6];
    const float* fw1 = (const float*)d_in[7];
    const float* fb1 = (const float*)d_in[8];
    const float* fw2 = (const float*)d_in[9];
    const float* fb2 = (const float*)d_in[10];
    float* out = (float*)d_out;

    cudaFuncSetAttribute(k_conv1, cudaFuncAttributeMaxDynamicSharedMemorySize, C1_SMEM);
    cudaFuncSetAttribute(k_conv2, cudaFuncAttributeMaxDynamicSharedMemorySize, C2_SMEM);
    cudaFuncSetAttribute(k_conv3, cudaFuncAttributeMaxDynamicSharedMemorySize, C3_SMEM);
    cudaFuncSetAttribute(k_fc1,   cudaFuncAttributeMaxDynamicSharedMemorySize, FC1_SMEM);

    k_prep<<<512, 256>>>(fw1, w2, w3);
    k_conv1<<<BATCH / 4, 512, C1_SMEM>>>(x, w1, b1);
    k_conv2<<<BATCH / 4, 512, C2_SMEM>>>(b2);
    k_conv3<<<dim3((BATCH + 2) / 3, 4), 320, C3_SMEM>>>(b3);
    k_fc1<<<dim3(2, BATCH / 128), 256, FC1_SMEM>>>(fb1);
    k_fc2<<<BATCH / 8, 256>>>(fw2, fb2, out);
}

// round 17
// speedup vs baseline: 1.2569x; 1.0024x over previous
#include <cuda_runtime.h>
#include <cuda_bf16.h>
#include <math.h>
#include <stdint.h>

#define BATCH 8192

// conv1/conv2/fc1 activations & weights: bf16 hi/lo interleaved groups of 4.
// conv3 path: TF32 (fp32 bit patterns, cvt.rna'd) with k-pair permutation
//   within each 8-chunk: position 2t <-> ic t, position 2t+1 <-> ic t+4.
__device__ __nv_bfloat16 g_a1[BATCH * 196 * 32];   // conv1 out: [b][px][16ic -> 32 elem]
__device__ float         g_a2f[BATCH * 49 * 32];   // conv2 out: [b][px][32 ic tf32, pair-permuted]
__device__ __nv_bfloat16 g_a3[BATCH * 2048];       // conv3 out: [b][1024k -> 2048 elem]
__device__ float g_a4[BATCH * 256];                // fc1 out
__device__ __nv_bfloat16 g_fw1[256 * 2048];        // fc1 W interleaved
__device__ __nv_bfloat16 g_w2i[32 * 800];          // conv2 W: [oc][off*32 + p*4]
__device__ float         g_w3f[64 * 800];          // conv3 W tf32: [oc][off*32 + chunk*8 + pairpos]

__device__ __forceinline__ uint16_t bfbits(__nv_bfloat16 x) {
    return *reinterpret_cast<uint16_t*>(&x);
}
__device__ __forceinline__ void bf16split(float v, __nv_bfloat16& h, __nv_bfloat16& l) {
    h = __float2bfloat16(v);
    l = __float2bfloat16(v - __bfloat162float(h));
}
__device__ __forceinline__ uint2 pack4(float v0, float v1) {
    __nv_bfloat16 h0, l0, h1, l1;
    bf16split(v0, h0, l0);
    bf16split(v1, h1, l1);
    uint2 r;
    r.x = (uint32_t)bfbits(h0) | ((uint32_t)bfbits(h1) << 16);
    r.y = (uint32_t)bfbits(l0) | ((uint32_t)bfbits(l1) << 16);
    return r;
}
__device__ __forceinline__ uint32_t f2tf32(float v) {
    uint32_t r;
    asm("cvt.rna.tf32.f32 %0, %1;" : "=r"(r) : "f"(v));
    return r;
}

__device__ __forceinline__ void mma_bf16(float* c,
                                         uint32_t a0, uint32_t a1, uint32_t a2, uint32_t a3,
                                         uint32_t b0, uint32_t b1) {
    asm("mma.sync.aligned.m16n8k16.row.col.f32.bf16.bf16.f32 "
        "{%0,%1,%2,%3}, {%4,%5,%6,%7}, {%8,%9}, {%0,%1,%2,%3};"
        : "+f"(c[0]), "+f"(c[1]), "+f"(c[2]), "+f"(c[3])
        : "r"(a0), "r"(a1), "r"(a2), "r"(a3), "r"(b0), "r"(b1));
}
__device__ __forceinline__ void mma_tf32(float* c,
                                         uint32_t a0, uint32_t a1, uint32_t a2, uint32_t a3,
                                         uint32_t b0, uint32_t b1) {
    asm("mma.sync.aligned.m16n8k8.row.col.f32.tf32.tf32.f32 "
        "{%0,%1,%2,%3}, {%4,%5,%6,%7}, {%8,%9}, {%0,%1,%2,%3};"
        : "+f"(c[0]), "+f"(c[1]), "+f"(c[2]), "+f"(c[3])
        : "r"(a0), "r"(a1), "r"(a2), "r"(a3), "r"(b0), "r"(b1));
}

__device__ __forceinline__ uint2 lds_u64(const __nv_bfloat16* p, int elem_idx) {
    return *reinterpret_cast<const uint2*>(p + elem_idx);
}
__device__ __forceinline__ uint2 lds_f2(const float* p, int elem_idx) {
    return *reinterpret_cast<const uint2*>(p + elem_idx);
}
__device__ __forceinline__ uint32_t lds_u16e(const __nv_bfloat16* p, int elem_idx) {
    return (uint32_t)*reinterpret_cast<const uint16_t*>(p + elem_idx);
}
__device__ __forceinline__ uint32_t pk(uint32_t lo, uint32_t hi) {
    return lo | (hi << 16);
}

// cp.async helpers (16B)
__device__ __forceinline__ void cp16(void* smem_dst, const void* gmem_src) {
    uint32_t d = (uint32_t)__cvta_generic_to_shared(smem_dst);
    asm volatile("cp.async.cg.shared.global [%0], [%1], 16;\n" :: "r"(d), "l"(gmem_src));
}
#define CP_COMMIT() asm volatile("cp.async.commit_group;\n" ::: "memory")
#define CP_WAIT(n)  asm volatile("cp.async.wait_group %0;\n" :: "n"(n) : "memory")

// ---------------- merged prep kernel ----------------
__global__ void __launch_bounds__(256) k_prep(const float* __restrict__ fw1,
                                              const float* __restrict__ w2,
                                              const float* __restrict__ w3) {
    int i = blockIdx.x * 256 + threadIdx.x;   // 131072 total
    {
        int row = i >> 9, p = i & 511;
        uint2 v = pack4(fw1[row * 1024 + 2 * p], fw1[row * 1024 + 2 * p + 1]);
        *reinterpret_cast<uint2*>(g_fw1 + row * 2048 + p * 4) = v;
    }
    if (i < 6400) {
        int oc = i / 200, r = i - oc * 200;
        int off = r >> 3, p = r & 7;
        uint2 v = pack4(w2[oc * 400 + (2 * p) * 25 + off], w2[oc * 400 + (2 * p + 1) * 25 + off]);
        *reinterpret_cast<uint2*>(g_w2i + oc * 800 + off * 32 + p * 4) = v;
    }
    if (i < 25600) {   // conv3 W: tf32 pair-permuted
        int oc = i / 400, r = i - oc * 400;
        int off = r >> 4, p = r & 15;
        int chunk = p >> 2, t = p & 3;
        int ic0 = chunk * 8 + t, ic1 = ic0 + 4;
        uint2 v;
        v.x = f2tf32(w3[oc * 800 + ic0 * 25 + off]);
        v.y = f2tf32(w3[oc * 800 + ic1 * 25 + off]);
        *reinterpret_cast<uint2*>(g_w3f + oc * 800 + off * 32 + chunk * 8 + 2 * t) = v;
    }
}

// ---------------- conv1 (1->16) via bf16x3 MMA, weights-as-A ----------------
#define C1_SMEM 70496
__global__ void __launch_bounds__(512) k_conv1(const float* __restrict__ x,
                                               const float* __restrict__ w1,
                                               const float* __restrict__ b1) {
    extern __shared__ char smem[];
    __nv_bfloat16* s_hi = (__nv_bfloat16*)(smem);            // 4488 elem (4 x 34x33)
    __nv_bfloat16* s_lo = (__nv_bfloat16*)(smem + 8976);     // 4488 elem
    __nv_bfloat16* s_w  = (__nv_bfloat16*)(smem + 17952);    // 16 x 72 elem interleaved
    int*           s_pool = (int*)(smem + 20256);            // 4*196*16
    float*         s_bias = (float*)(smem + 70432);

    const int img0 = blockIdx.x * 4;
    const int tid = threadIdx.x;
    const int warp = tid >> 5;
    const int lane = tid & 31;
    const int gid = lane >> 2;
    const int tg  = lane & 3;

    for (int i = tid; i < 4488; i += 512) ((uint32_t*)smem)[i] = 0u;
    for (int i = tid; i < 12544; i += 512) s_pool[i] = 0;
    if (tid < 16) s_bias[tid] = b1[tid];
    if (tid < 256) {
        int oc = tid >> 4, p = tid & 15;
        int k0 = 2 * p, k1 = 2 * p + 1;
        float v0 = (k0 < 25) ? w1[oc * 25 + k0] : 0.f;
        float v1 = (k1 < 25) ? w1[oc * 25 + k1] : 0.f;
        *reinterpret_cast<uint2*>(s_w + oc * 72 + p * 4) = pack4(v0, v1);
    }
    __syncthreads();
    for (int i = tid; i < 3136; i += 512) {
        int img = i / 784, px = i - img * 784;
        int iy = px / 28, ix = px - iy * 28;
        __nv_bfloat16 h, l;
        bf16split(x[(img0 + img) * 784 + px], h, l);
        int d = img * 1122 + (iy + 2) * 33 + (ix + 2);
        s_hi[d] = h; s_lo[d] = l;
    }
    __syncthreads();

    uint32_t Ah[2][4], Al[2][4];
#pragma unroll
    for (int s = 0; s < 2; s++) {
        uint2 g0 = lds_u64(s_w, gid * 72 + (tg + 8 * s) * 4);
        uint2 g1 = lds_u64(s_w, (gid + 8) * 72 + (tg + 8 * s) * 4);
        uint2 g2 = lds_u64(s_w, gid * 72 + (tg + 4 + 8 * s) * 4);
        uint2 g3 = lds_u64(s_w, (gid + 8) * 72 + (tg + 4 + 8 * s) * 4);
        Ah[s][0] = g0.x; Al[s][0] = g0.y;
        Ah[s][1] = g1.x; Al[s][1] = g1.y;
        Ah[s][2] = g2.x; Al[s][2] = g2.y;
        Ah[s][3] = g3.x; Al[s][3] = g3.y;
    }

    int doff[8];
    {
        int kk[8] = {2 * tg, 2 * tg + 1, 2 * tg + 8, 2 * tg + 9,
                     2 * tg + 16, 2 * tg + 17, 2 * tg + 24, 2 * tg + 25};
#pragma unroll
        for (int j = 0; j < 8; j++) {
            int ky = kk[j] / 5, kx = kk[j] - ky * 5;
            doff[j] = ky * 33 + kx;
        }
    }

    const float bb0 = s_bias[gid], bb1 = s_bias[gid + 8];

#pragma unroll 1
    for (int ti = 0; ti < 13; ti++) {
#pragma unroll
        for (int half = 0; half < 2; half++) {
            int t = warp + 16 * (2 * ti + half);
            if (t < 392) {
                int img = t / 98, tb = t - img * 98;
                int pxg = tb * 8 + gid;
                int yg = pxg / 28, xg = pxg - yg * 28;
                int ab = img * 1122 + yg * 33 + xg;

                uint32_t bh0 = pk(lds_u16e(s_hi, ab + doff[0]), lds_u16e(s_hi, ab + doff[1]));
                uint32_t bh1 = pk(lds_u16e(s_hi, ab + doff[2]), lds_u16e(s_hi, ab + doff[3]));
                uint32_t bh2 = pk(lds_u16e(s_hi, ab + doff[4]), lds_u16e(s_hi, ab + doff[5]));
                uint32_t bh3 = pk(lds_u16e(s_hi, ab + doff[6]), lds_u16e(s_hi, ab + doff[7]));
                uint32_t bl0 = pk(lds_u16e(s_lo, ab + doff[0]), lds_u16e(s_lo, ab + doff[1]));
                uint32_t bl1 = pk(lds_u16e(s_lo, ab + doff[2]), lds_u16e(s_lo, ab + doff[3]));
                uint32_t bl2 = pk(lds_u16e(s_lo, ab + doff[4]), lds_u16e(s_lo, ab + doff[5]));
                uint32_t bl3 = pk(lds_u16e(s_lo, ab + doff[6]), lds_u16e(s_lo, ab + doff[7]));

                float c[4] = {0.f, 0.f, 0.f, 0.f};
                mma_bf16(c, Ah[0][0], Ah[0][1], Ah[0][2], Ah[0][3], bh0, bh1);
                mma_bf16(c, Ah[1][0], Ah[1][1], Ah[1][2], Ah[1][3], bh2, bh3);
                mma_bf16(c, Ah[0][0], Ah[0][1], Ah[0][2], Ah[0][3], bl0, bl1);
                mma_bf16(c, Ah[1][0], Ah[1][1], Ah[1][2], Ah[1][3], bl2, bl3);
                mma_bf16(c, Al[0][0], Al[0][1], Al[0][2], Al[0][3], bh0, bh1);
                mma_bf16(c, Al[1][0], Al[1][1], Al[1][2], Al[1][3], bh2, bh3);

                int pxo = tb * 8 + 2 * tg;
                int yo = pxo / 28, xo = pxo - yo * 28;
                int sp = (yo >> 1) * 14 + (xo >> 1);
                float v0 = fmaxf(c[0] + bb0, 0.f);
                float v1 = fmaxf(c[1] + bb0, 0.f);
                float v2 = fmaxf(c[2] + bb1, 0.f);
                float v3 = fmaxf(c[3] + bb1, 0.f);
                atomicMax(&s_pool[img * 3136 + sp * 16 + gid], __float_as_int(fmaxf(v0, v1)));
                atomicMax(&s_pool[img * 3136 + sp * 16 + gid + 8], __float_as_int(fmaxf(v2, v3)));
            }
        }
    }
    __syncthreads();
    for (int i = tid; i < 6272; i += 512) {
        int img = i / 1568, rr = i - img * 1568;
        int sp = rr >> 3, p = rr & 7;
        float v0 = __int_as_float(s_pool[img * 3136 + sp * 16 + 2 * p]);
        float v1 = __int_as_float(s_pool[img * 3136 + sp * 16 + 2 * p + 1]);
        *reinterpret_cast<uint2*>(g_a1 + ((img0 + img) * 196 + sp) * 32 + p * 4) = pack4(v0, v1);
    }
}

// ---------------- conv2 (16->32): 4 img/block, 512 thr, full unroll ----------------
#define C2_SMEM 201984
__global__ void __launch_bounds__(512) k_conv2(const float* __restrict__ b2) {
    extern __shared__ char smem[];
    __nv_bfloat16* s_in = (__nv_bfloat16*)(smem);               // 62208 elem
    __nv_bfloat16* s_w  = (__nv_bfloat16*)(smem + 124416);      // 26112 elem
    int*           s_pool = (int*)(smem + 176640);              // 6272 int
    float*         s_bias = (float*)(smem + 201728);

    const int img0 = blockIdx.x * 4;
    const int tid = threadIdx.x;
    const int warp = tid >> 5;
    const int lane = tid & 31;
    const int gid = lane >> 2;
    const int tg  = lane & 3;
    const int kq  = tg * 4;

    uint4 z4 = {0, 0, 0, 0};
    for (int i = tid; i < 7776; i += 512) ((uint4*)s_in)[i] = z4;
    for (int i = tid; i < 6272; i += 512) s_pool[i] = 0;
    if (tid < 32) s_bias[tid] = b2[tid];
    __syncthreads();
    for (int i = tid; i < 3200; i += 512) {
        int oc = i / 100, r = i - oc * 100;
        cp16(s_w + oc * 816 + r * 8, g_w2i + oc * 800 + r * 8);
    }
    for (int i = tid; i < 3136; i += 512) {
        int img = i / 784, r = i - img * 784;
        int px = r >> 2, q = r & 3;
        int y = px / 14, xx = px - y * 14;
        cp16(s_in + img * 15552 + ((y + 2) * 18 + (xx + 2)) * 48 + q * 8,
             g_a1 + ((img0 + img) * 196 + px) * 32 + q * 8);
    }
    CP_COMMIT();
    CP_WAIT(0);
    __syncthreads();

    int aoff0[4], aoff1[4];
#pragma unroll
    for (int ti = 0; ti < 4; ti++) {
        int t = warp + 16 * ti;
        if (t < 49) {
            int r0 = t * 16 + gid, r1 = r0 + 8;
            int i0 = r0 / 196, p0 = r0 - i0 * 196;
            int i1 = r1 / 196, p1 = r1 - i1 * 196;
            int y0 = p0 / 14, x0 = p0 - y0 * 14;
            int y1 = p1 / 14, x1 = p1 - y1 * 14;
            aoff0[ti] = i0 * 15552 + (y0 * 18 + x0) * 48 + kq;
            aoff1[ti] = i1 * 15552 + (y1 * 18 + x1) * 48 + kq;
        }
    }

    float acc[4][4][4];
#pragma unroll
    for (int ti = 0; ti < 4; ti++)
#pragma unroll
        for (int nt = 0; nt < 4; nt++)
#pragma unroll
            for (int j = 0; j < 4; j++) acc[ti][nt][j] = 0.f;

    int wrb[4];
#pragma unroll
    for (int nt = 0; nt < 4; nt++) wrb[nt] = (nt * 8 + gid) * 816 + kq;

#pragma unroll
    for (int off = 0; off < 25; off++) {
        const int dy = off / 5, dx = off - dy * 5;
        const int dpix = (dy * 18 + dx) * 48;
        const int wofs = off * 32;
        uint32_t bh0[4], bh1[4], bl0[4], bl1[4];
#pragma unroll
        for (int nt = 0; nt < 4; nt++) {
            uint2 w0 = lds_u64(s_w, wrb[nt] + wofs);
            uint2 w1 = lds_u64(s_w, wrb[nt] + wofs + 16);
            bh0[nt] = w0.x; bl0[nt] = w0.y;
            bh1[nt] = w1.x; bl1[nt] = w1.y;
        }
#pragma unroll
        for (int ti = 0; ti < 4; ti++) {
            int t = warp + 16 * ti;
            if (t < 49) {
                int o0 = aoff0[ti] + dpix;
                int o1 = aoff1[ti] + dpix;
                uint2 a00 = lds_u64(s_in, o0);
                uint2 a01 = lds_u64(s_in, o1);
                uint2 a02 = lds_u64(s_in, o0 + 16);
                uint2 a03 = lds_u64(s_in, o1 + 16);
#pragma unroll
                for (int nt = 0; nt < 4; nt++)
                    mma_bf16(acc[ti][nt], a00.x, a01.x, a02.x, a03.x, bh0[nt], bh1[nt]);
#pragma unroll
                for (int nt = 0; nt < 4; nt++)
                    mma_bf16(acc[ti][nt], a00.x, a01.x, a02.x, a03.x, bl0[nt], bl1[nt]);
#pragma unroll
                for (int nt = 0; nt < 4; nt++)
                    mma_bf16(acc[ti][nt], a00.y, a01.y, a02.y, a03.y, bh0[nt], bh1[nt]);
            }
        }
    }

#pragma unroll
    for (int ti = 0; ti < 4; ti++) {
        int t = warp + 16 * ti;
        if (t < 49) {
            int r0 = t * 16 + gid, r1 = r0 + 8;
            int i0 = r0 / 196, p0 = r0 - i0 * 196;
            int i1 = r1 / 196, p1 = r1 - i1 * 196;
            int y0 = p0 / 14, x0 = p0 - y0 * 14;
            int y1 = p1 / 14, x1 = p1 - y1 * 14;
            int pi0 = i0 * 1568 + ((y0 >> 1) * 7 + (x0 >> 1)) * 32;
            int pi1 = i1 * 1568 + ((y1 >> 1) * 7 + (x1 >> 1)) * 32;
#pragma unroll
            for (int nt = 0; nt < 4; nt++) {
                int col = nt * 8 + tg * 2;
                float bb0 = s_bias[col], bb1 = s_bias[col + 1];
                float v0 = fmaxf(acc[ti][nt][0] + bb0, 0.f);
                float v1 = fmaxf(acc[ti][nt][1] + bb1, 0.f);
                float v2 = fmaxf(acc[ti][nt][2] + bb0, 0.f);
                float v3 = fmaxf(acc[ti][nt][3] + bb1, 0.f);
                float q0 = __shfl_xor_sync(0xffffffffu, v0, 4);
                float q1 = __shfl_xor_sync(0xffffffffu, v1, 4);
                float q2 = __shfl_xor_sync(0xffffffffu, v2, 4);
                float q3 = __shfl_xor_sync(0xffffffffu, v3, 4);
                if ((gid & 1) == 0) {
                    atomicMax(&s_pool[pi0 + col], __float_as_int(fmaxf(v0, q0)));
                    atomicMax(&s_pool[pi0 + col + 1], __float_as_int(fmaxf(v1, q1)));
                    atomicMax(&s_pool[pi1 + col], __float_as_int(fmaxf(v2, q2)));
                    atomicMax(&s_pool[pi1 + col + 1], __float_as_int(fmaxf(v3, q3)));
                }
            }
        }
    }
    __syncthreads();
    // write g_a2f: tf32, pair-permuted within each 8-chunk
    for (int i = tid; i < 3136; i += 512) {
        int img = i / 784, r = i - img * 784;
        int px = r >> 4, j = r & 15;
        int chunk = j >> 2, t = j & 3;
        int ic0 = chunk * 8 + t, ic1 = ic0 + 4;
        uint2 v;
        v.x = f2tf32(__int_as_float(s_pool[img * 1568 + px * 32 + ic0]));
        v.y = f2tf32(__int_as_float(s_pool[img * 1568 + px * 32 + ic1]));
        *reinterpret_cast<uint2*>(g_a2f + ((img0 + img) * 49 + px) * 32 + chunk * 8 + 2 * t) = v;
    }
}

// ---------------- conv3 (32->64) via TF32 MMA: 3 img x 16-oc, 320 thr ----------------
// smem: in 3*4840 fp32 (58080B) | w 16*808 fp32 (51712B) | pool 768 int | bias 64
#define C3_SMEM (58080 + 51712 + 3072 + 64)
__global__ void __launch_bounds__(320) k_conv3(const float* __restrict__ b3) {
    extern __shared__ char smem[];
    float* s_in = (float*)(smem);                 // 14520 fp32 (3 x 121px x 40)
    float* s_w  = (float*)(smem + 58080);         // 16 x 808 fp32
    int*   s_pool = (int*)(smem + 109792);        // 768 int
    float* s_bias = (float*)(smem + 112864);      // 16

    const int img0 = blockIdx.x * 3;
    const int g = blockIdx.y;        // oc-group 0..3 (16 oc each)
    const int tid = threadIdx.x;
    const int warp = tid >> 5;       // 0..9 -> m-tile
    const int lane = tid & 31;
    const int gid = lane >> 2;
    const int tg  = lane & 3;

    uint4 z4 = {0, 0, 0, 0};
    for (int i = tid; i < 3630; i += 320) ((uint4*)s_in)[i] = z4;
    for (int i = tid; i < 768; i += 320) s_pool[i] = 0;
    if (tid < 16) s_bias[tid] = b3[g * 16 + tid];
    __syncthreads();
    const float* wg = g_w3f + g * 16 * 800;
    for (int i = tid; i < 3200; i += 320) {
        int ocl = i / 200, r = i - ocl * 200;
        cp16(s_w + ocl * 808 + r * 4, wg + ocl * 800 + r * 4);
    }
    for (int i = tid; i < 1176; i += 320) {
        int img = i / 392, r = i - img * 392;
        if (img0 + img < BATCH) {
            int px = r >> 3, q = r & 7;
            int y = px / 7, xx = px - y * 7;
            cp16(s_in + img * 4840 + ((y + 2) * 11 + (xx + 2)) * 40 + q * 4,
                 g_a2f + ((img0 + img) * 49 + px) * 32 + q * 4);
        }
    }
    CP_COMMIT();
    CP_WAIT(0);
    __syncthreads();

    int r0 = warp * 16 + gid, r1 = r0 + 8;
    int rc0 = r0 < 146 ? r0 : 146;
    int rc1 = r1 < 146 ? r1 : 146;
    int i0 = rc0 / 49, p0 = rc0 - i0 * 49;
    int i1 = rc1 / 49, p1 = rc1 - i1 * 49;
    int y0 = p0 / 7, x0 = p0 - y0 * 7;
    int y1 = p1 / 7, x1 = p1 - y1 * 7;
    const int aoff0 = i0 * 4840 + (y0 * 11 + x0) * 40 + 2 * tg;
    const int aoff1 = i1 * 4840 + (y1 * 11 + x1) * 40 + 2 * tg;
    const int wb0 = gid * 808 + 2 * tg;
    const int wb1 = (8 + gid) * 808 + 2 * tg;

    float acc[2][4];
#pragma unroll
    for (int nt = 0; nt < 2; nt++)
#pragma unroll
        for (int j = 0; j < 4; j++) acc[nt][j] = 0.f;

#pragma unroll
    for (int off = 0; off < 25; off++) {
        const int dy = off / 5, dx = off - dy * 5;      // compile-time after unroll
        const int dpix = (dy * 11 + dx) * 40;
        const int wofs = off * 32;
#pragma unroll
        for (int c = 0; c < 4; c++) {
            // A fragments: {k=tg, k=tg+4} adjacent via pair permutation
            uint2 u0 = lds_f2(s_in, aoff0 + dpix + c * 8);
            uint2 u1 = lds_f2(s_in, aoff1 + dpix + c * 8);
            uint2 w0 = lds_f2(s_w, wb0 + wofs + c * 8);
            uint2 w1 = lds_f2(s_w, wb1 + wofs + c * 8);
            mma_tf32(acc[0], u0.x, u1.x, u0.y, u1.y, w0.x, w0.y);
            mma_tf32(acc[1], u0.x, u1.x, u0.y, u1.y, w1.x, w1.y);
        }
    }

    // epilogue: bias + relu, pool (pad=1)
    {
        bool v0 = (r0 < 147) && (img0 + i0 < BATCH);
        bool v1 = (r1 < 147) && (img0 + i1 < BATCH);
        int pi0 = i0 * 256 + (((y0 + 1) >> 1) * 4 + ((x0 + 1) >> 1)) * 16;
        int pi1 = i1 * 256 + (((y1 + 1) >> 1) * 4 + ((x1 + 1) >> 1)) * 16;
#pragma unroll
        for (int nt = 0; nt < 2; nt++) {
            int col = nt * 8 + tg * 2;
            float bb0 = s_bias[col], bb1 = s_bias[col + 1];
            if (v0) {
                atomicMax(&s_pool[pi0 + col], __float_as_int(fmaxf(acc[nt][0] + bb0, 0.f)));
                atomicMax(&s_pool[pi0 + col + 1], __float_as_int(fmaxf(acc[nt][1] + bb1, 0.f)));
            }
            if (v1) {
                atomicMax(&s_pool[pi1 + col], __float_as_int(fmaxf(acc[nt][2] + bb0, 0.f)));
                atomicMax(&s_pool[pi1 + col + 1], __float_as_int(fmaxf(acc[nt][3] + bb1, 0.f)));
            }
        }
    }
    __syncthreads();
    // g_a3: standard bf16 hi/lo interleave (fc1 convention)
    for (int i = tid; i < 384; i += 320) {
        int img = i >> 7, r = i & 127;
        if (img0 + img < BATCH) {
            int ocl = r >> 3, pp = r & 7;
            float v0 = __int_as_float(s_pool[img * 256 + (2 * pp) * 16 + ocl]);
            float v1 = __int_as_float(s_pool[img * 256 + (2 * pp + 1) * 16 + ocl]);
            int gp = (g * 16 + ocl) * 8 + pp;
            *reinterpret_cast<uint2*>(g_a3 + (img0 + img) * 2048 + gp * 4) = pack4(v0, v1);
        }
    }
}

// ---------------- fc1 via bf16x3 MMA, cp.async double-buffered ----------------
#define FC1_STRIDE 144
#define FC1_STAGE (128 * FC1_STRIDE)
#define FC1_SMEM (4 * FC1_STAGE * 2)
__global__ void __launch_bounds__(256) k_fc1(const float* __restrict__ bias) {
    extern __shared__ char smem[];
    __nv_bfloat16* s_base = (__nv_bfloat16*)smem;
    const int tid = threadIdx.x;
    const int warp = tid >> 5, lane = tid & 31;
    const int wm = warp >> 1, wn = warp & 1;
    const int m0 = blockIdx.y * 128, n0 = blockIdx.x * 128;
    const int gid = lane >> 2, tg = lane & 3;
    const int kq = tg * 4;

    float acc[2][8][4];
#pragma unroll
    for (int mt = 0; mt < 2; mt++)
#pragma unroll
        for (int nt = 0; nt < 8; nt++)
#pragma unroll
            for (int j = 0; j < 4; j++) acc[mt][nt][j] = 0.f;

    auto load_stage = [&](int stage, int k0e) {
        __nv_bfloat16* s_a = s_base + stage * 2 * FC1_STAGE;
        __nv_bfloat16* s_b = s_a + FC1_STAGE;
        for (int i = tid; i < 4096; i += 256) {
            int j = i & 2047;
            int row = j >> 4, q = j & 15;
            int dst = row * FC1_STRIDE + q * 8;
            if (i < 2048)
                cp16(s_a + dst, g_a3 + (m0 + row) * 2048 + k0e + q * 8);
            else
                cp16(s_b + dst, g_fw1 + (n0 + row) * 2048 + k0e + q * 8);
        }
        CP_COMMIT();
    };

    load_stage(0, 0);

#pragma unroll 1
    for (int k = 0; k < 16; k++) {
        if (k < 15) load_stage((k + 1) & 1, (k + 1) * 128);
        if (k < 15) { CP_WAIT(1); } else { CP_WAIT(0); }
        __syncthreads();
        __nv_bfloat16* s_a = s_base + (k & 1) * 2 * FC1_STAGE;
        __nv_bfloat16* s_b = s_a + FC1_STAGE;
#pragma unroll
        for (int ks = 0; ks < 4; ks++) {
            int kb = ks * 32 + kq;
            uint32_t ah[2][4], al[2][4];
#pragma unroll
            for (int mt = 0; mt < 2; mt++) {
                int base = (wm * 32 + mt * 16 + gid) * FC1_STRIDE + kb;
                uint2 q0 = lds_u64(s_a, base);
                uint2 q1 = lds_u64(s_a, base + 8 * FC1_STRIDE);
                uint2 q2 = lds_u64(s_a, base + 16);
                uint2 q3 = lds_u64(s_a, base + 8 * FC1_STRIDE + 16);
                ah[mt][0] = q0.x; al[mt][0] = q0.y;
                ah[mt][1] = q1.x; al[mt][1] = q1.y;
                ah[mt][2] = q2.x; al[mt][2] = q2.y;
                ah[mt][3] = q3.x; al[mt][3] = q3.y;
            }
            uint32_t bh[8][2], bl[8][2];
#pragma unroll
            for (int nt = 0; nt < 8; nt++) {
                int base = (wn * 64 + nt * 8 + gid) * FC1_STRIDE + kb;
                uint2 w0 = lds_u64(s_b, base);
                uint2 w1 = lds_u64(s_b, base + 16);
                bh[nt][0] = w0.x; bl[nt][0] = w0.y;
                bh[nt][1] = w1.x; bl[nt][1] = w1.y;
            }
#pragma unroll
            for (int mt = 0; mt < 2; mt++) {
#pragma unroll
                for (int nt = 0; nt < 8; nt++)
                    mma_bf16(acc[mt][nt], ah[mt][0], ah[mt][1], ah[mt][2], ah[mt][3], bh[nt][0], bh[nt][1]);
#pragma unroll
                for (int nt = 0; nt < 8; nt++)
                    mma_bf16(acc[mt][nt], ah[mt][0], ah[mt][1], ah[mt][2], ah[mt][3], bl[nt][0], bl[nt][1]);
#pragma unroll
                for (int nt = 0; nt < 8; nt++)
                    mma_bf16(acc[mt][nt], al[mt][0], al[mt][1], al[mt][2], al[mt][3], bh[nt][0], bh[nt][1]);
            }
        }
        __syncthreads();
    }
#pragma unroll
    for (int mt = 0; mt < 2; mt++) {
        int r = m0 + wm * 32 + mt * 16 + gid;
#pragma unroll
        for (int nt = 0; nt < 8; nt++) {
            int c = n0 + wn * 64 + nt * 8 + tg * 2;
            float b0 = bias[c], b1 = bias[c + 1];
            g_a4[r * 256 + c]           = fmaxf(acc[mt][nt][0] + b0, 0.f);
            g_a4[r * 256 + c + 1]       = fmaxf(acc[mt][nt][1] + b1, 0.f);
            g_a4[(r + 8) * 256 + c]     = fmaxf(acc[mt][nt][2] + b0, 0.f);
            g_a4[(r + 8) * 256 + c + 1] = fmaxf(acc[mt][nt][3] + b1, 0.f);
        }
    }
}

// ---------------- fc2 + log_softmax ----------------
__global__ void __launch_bounds__(256) k_fc2(const float* __restrict__ W,
                                             const float* __restrict__ bias,
                                             float* __restrict__ out) {
    __shared__ float s_w[2560];
    __shared__ float s_b[10];
    const int tid = threadIdx.x;
    for (int i = tid; i < 2560; i += 256) s_w[i] = W[i];
    if (tid < 10) s_b[tid] = bias[tid];
    __syncthreads();

    const int warp = tid >> 5, lane = tid & 31;
    const int row = blockIdx.x * 8 + warp;
    float hv[8];
    const float* hp = g_a4 + row * 256 + lane;
#pragma unroll
    for (int j = 0; j < 8; j++) hv[j] = hp[j * 32];

    float acc[10];
#pragma unroll
    for (int o = 0; o < 10; o++) acc[o] = 0.f;
#pragma unroll
    for (int j = 0; j < 8; j++) {
#pragma unroll
        for (int o = 0; o < 10; o++)
            acc[o] += hv[j] * s_w[o * 256 + lane + j * 32];
    }
#pragma unroll
    for (int o = 0; o < 10; o++) {
#pragma unroll
        for (int off = 16; off > 0; off >>= 1)
            acc[o] += __shfl_xor_sync(0xffffffffu, acc[o], off);
    }
    if (lane == 0) {
        float l[10], m = -1e30f;
#pragma unroll
        for (int o = 0; o < 10; o++) { l[o] = acc[o] + s_b[o]; m = fmaxf(m, l[o]); }
        float s = 0.f;
#pragma unroll
        for (int o = 0; o < 10; o++) s += expf(l[o] - m);
        float ls = logf(s);
        float* op = out + row * 10;
#pragma unroll
        for (int o = 0; o < 10; o++) op[o] = l[o] - m - ls;
    }
}

extern "C" void kernel_launch(void* const* d_in, const int* in_sizes, int n_in,
                              void* d_out, int out_size) {
    const float* x   = (const float*)d_in[0];
    const float* w1  = (const float*)d_in[1];
    const float* b1  = (const float*)d_in[2];
    const float* w2  = (const float*)d_in[3];
    const float* b2  = (const float*)d_in[4];
    const float* w3  = (const float*)d_in[5];
    const float* b3  = (const float*)d_in[6];
    const float* fw1 = (const float*)d_in[7];
    const float* fb1 = (const float*)d_in[8];
    const float* fw2 = (const float*)d_in[9];
    const float* fb2 = (const float*)d_in[10];
    float* out = (float*)d_out;

    cudaFuncSetAttribute(k_conv1, cudaFuncAttributeMaxDynamicSharedMemorySize, C1_SMEM);
    cudaFuncSetAttribute(k_conv2, cudaFuncAttributeMaxDynamicSharedMemorySize, C2_SMEM);
    cudaFuncSetAttribute(k_conv3, cudaFuncAttributeMaxDynamicSharedMemorySize, C3_SMEM);
    cudaFuncSetAttribute(k_fc1,   cudaFuncAttributeMaxDynamicSharedMemorySize, FC1_SMEM);

    k_prep<<<512, 256>>>(fw1, w2, w3);
    k_conv1<<<BATCH / 4, 512, C1_SMEM>>>(x, w1, b1);
    k_conv2<<<BATCH / 4, 512, C2_SMEM>>>(b2);
    k_conv3<<<dim3((BATCH + 2) / 3, 4), 320, C3_SMEM>>>(b3);
    k_fc1<<<dim3(2, BATCH / 128), 256, FC1_SMEM>>>(fb1);
    k_fc2<<<BATCH / 8, 256>>>(fw2, fb2, out);
}